// round 1
// baseline (speedup 1.0000x reference)
#include <cuda_runtime.h>
#include <math.h>

#define L_   12
#define S_   512
#define B_   4
#define DIN_ 768
#define D_   1024
#define H_   16
#define F_   4096
#define HD_  64
#define SB_  2048        // S*B rows
#define BH_  (B_*H_)

// ---------------- scratch (device globals: allocation-free) ----------------
__device__ float g_h   [SB_*D_];                 // LN output
__device__ float g_q   [SB_*D_];
__device__ float g_k   [SB_*D_];
__device__ float g_v   [SB_*D_];
__device__ float g_attn[SB_*D_];
__device__ float g_ff  [(size_t)SB_*F_];         // 32 MB
__device__ float g_scores[(size_t)BH_*S_*S_];    // 64 MB
__device__ int   g_mask_mode;                    // 0=u8, 1=i32, 2=f32

// ---------------- mask dtype detection (reads exactly 2048 bytes) ----------
__global__ void detect_mask_kernel(const void* m) {
    __shared__ int flags[2];
    if (threadIdx.x == 0) { flags[0] = 0; flags[1] = 0; }
    __syncthreads();
    unsigned v = ((const unsigned*)m)[threadIdx.x];   // 512 words = 2048 bytes (B*S bools)
    if (v > 1u) flags[0] = 1;                          // not all {0,1} -> not int32
    if (v != 0u && v != 0x3F800000u) flags[1] = 1;     // not all {0,1.0f} -> not float32
    __syncthreads();
    if (threadIdx.x == 0)
        g_mask_mode = (!flags[0]) ? 1 : ((!flags[1]) ? 2 : 0);
}

// ---------------- generic fp32 GEMM: C = A[M,K] @ W[K,N] (+bias, epilogue) --
// MODE 0: C = acc+bias   MODE 1: C += acc+bias (residual)   MODE 2: C = gelu(acc+bias)
template<int MODE>
__global__ __launch_bounds__(256) void gemm_kernel(
    const float* __restrict__ A, const float* __restrict__ W,
    const float* __restrict__ bias, float* __restrict__ C,
    int M, int N, int K)
{
    const int BK = 16;
    __shared__ float As[16][128];   // transposed A tile
    __shared__ float Ws[16][128];
    int tid = threadIdx.x;
    int tx = tid & 15, ty = tid >> 4;
    int rowBase = blockIdx.y * 128, colBase = blockIdx.x * 128;

    float acc[8][8];
#pragma unroll
    for (int i = 0; i < 8; i++)
#pragma unroll
        for (int j = 0; j < 8; j++) acc[i][j] = 0.f;

    for (int k0 = 0; k0 < K; k0 += BK) {
#pragma unroll
        for (int it = 0; it < 2; it++) {
            int e = tid + it * 256;
            int r = e >> 2, c = (e & 3) << 2;
            float4 v = *(const float4*)(A + (size_t)(rowBase + r) * K + k0 + c);
            As[c + 0][r] = v.x; As[c + 1][r] = v.y; As[c + 2][r] = v.z; As[c + 3][r] = v.w;
        }
#pragma unroll
        for (int it = 0; it < 2; it++) {
            int e = tid + it * 256;
            int r = e >> 5, c = (e & 31) << 2;
            *(float4*)(&Ws[r][c]) = *(const float4*)(W + (size_t)(k0 + r) * N + colBase + c);
        }
        __syncthreads();
#pragma unroll
        for (int kk = 0; kk < BK; kk++) {
            float ar[8], br[8];
#pragma unroll
            for (int i = 0; i < 8; i++) ar[i] = As[kk][ty * 8 + i];
#pragma unroll
            for (int j = 0; j < 8; j++) br[j] = Ws[kk][tx * 8 + j];
#pragma unroll
            for (int i = 0; i < 8; i++)
#pragma unroll
                for (int j = 0; j < 8; j++)
                    acc[i][j] = fmaf(ar[i], br[j], acc[i][j]);
        }
        __syncthreads();
    }

#pragma unroll
    for (int i = 0; i < 8; i++) {
        int row = rowBase + ty * 8 + i;
#pragma unroll
        for (int j = 0; j < 8; j++) {
            int col = colBase + tx * 8 + j;
            float v = acc[i][j] + bias[col];
            size_t idx = (size_t)row * N + col;
            if (MODE == 0)      C[idx] = v;
            else if (MODE == 1) C[idx] += v;
            else                C[idx] = 0.5f * v * (1.f + erff(v * 0.70710678118654752f));
        }
    }
}

// ---------------- LayerNorm: one block per row of 1024 ----------------------
__global__ __launch_bounds__(256) void ln_kernel(
    const float* __restrict__ x, const float* __restrict__ g,
    const float* __restrict__ b, float* __restrict__ out)
{
    int row = blockIdx.x;
    int tid = threadIdx.x;
    const float* xr = x + (size_t)row * D_;
    float4 v = *(const float4*)(xr + tid * 4);
    float s  = v.x + v.y + v.z + v.w;
    float s2 = v.x * v.x + v.y * v.y + v.z * v.z + v.w * v.w;
    __shared__ float r1[256], r2[256];
    r1[tid] = s; r2[tid] = s2;
    __syncthreads();
    for (int off = 128; off > 0; off >>= 1) {
        if (tid < off) { r1[tid] += r1[tid + off]; r2[tid] += r2[tid + off]; }
        __syncthreads();
    }
    float mean = r1[0] * (1.f / D_);
    float var  = r2[0] * (1.f / D_) - mean * mean;
    float rstd = rsqrtf(var + 1e-5f);
    float4 gv = *(const float4*)(g + tid * 4);
    float4 bv = *(const float4*)(b + tid * 4);
    float4 o;
    o.x = (v.x - mean) * rstd * gv.x + bv.x;
    o.y = (v.y - mean) * rstd * gv.y + bv.y;
    o.z = (v.z - mean) * rstd * gv.z + bv.z;
    o.w = (v.w - mean) * rstd * gv.w + bv.w;
    *(float4*)(out + (size_t)row * D_ + tid * 4) = o;
}

// ---------------- RoPE in place on [S,B,D] laid-out q/k ---------------------
__global__ void rope_kernel(float* __restrict__ q) {
    int idx = blockIdx.x * blockDim.x + threadIdx.x;  // SB_*H_*32 threads
    int i = idx & 31;
    int h = (idx >> 5) & (H_ - 1);
    int r = idx >> 9;                 // row = s*B + b
    int s = r >> 2;                   // / B_
    // inv_freq = 10000^{-i/32} = exp(-ln(10000)/32 * i)
    float inv = expf(-0.28782313662425572f * (float)i);
    float ang = (float)s * inv;
    float c, sn;
    sincosf(ang, &sn, &c);
    float* base = q + (size_t)r * D_ + h * HD_ + i;
    float x1 = base[0], x2 = base[32];
    base[0]  = x1 * c - x2 * sn;
    base[32] = x2 * c + x1 * sn;
}

// ---------------- input-proj extra: x += dur[r]*Wdur[c] + bdur[c] -----------
__global__ void adddur_kernel(float* __restrict__ x, const float* __restrict__ dur,
                              const float* __restrict__ wd, const float* __restrict__ bd) {
    int idx = blockIdx.x * blockDim.x + threadIdx.x;  // SB_*D_
    int r = idx >> 10, c = idx & 1023;
    x[idx] += dur[r] * wd[c] + bd[c];
}

// ---------------- attention: scores = q @ k^T (per b,h) ---------------------
__global__ __launch_bounds__(256) void scores_kernel(
    const float* __restrict__ q, const float* __restrict__ k,
    float* __restrict__ scores)
{
    int bh = blockIdx.z;
    int b = bh >> 4, h = bh & 15;
    int q0 = blockIdx.y << 6, k0 = blockIdx.x << 6;
    __shared__ float Qs[64][65], Ks[64][65];
    int tid = threadIdx.x;
    const float* qb = q + (size_t)b * D_ + h * HD_;
    const float* kb = k + (size_t)b * D_ + h * HD_;
#pragma unroll
    for (int it = 0; it < 4; it++) {
        int e = tid + it * 256;
        int r = e >> 4, c = (e & 15) << 2;
        float4 v = *(const float4*)(qb + (size_t)(q0 + r) * (B_ * D_) + c);
        Qs[r][c] = v.x; Qs[r][c + 1] = v.y; Qs[r][c + 2] = v.z; Qs[r][c + 3] = v.w;
        float4 w = *(const float4*)(kb + (size_t)(k0 + r) * (B_ * D_) + c);
        Ks[r][c] = w.x; Ks[r][c + 1] = w.y; Ks[r][c + 2] = w.z; Ks[r][c + 3] = w.w;
    }
    __syncthreads();
    int tx = tid & 15, ty = tid >> 4;
    float acc[4][4] = {};
#pragma unroll 16
    for (int d = 0; d < 64; d++) {
        float a[4], bb[4];
#pragma unroll
        for (int i = 0; i < 4; i++) a[i]  = Qs[ty * 4 + i][d];
#pragma unroll
        for (int j = 0; j < 4; j++) bb[j] = Ks[tx * 4 + j][d];
#pragma unroll
        for (int i = 0; i < 4; i++)
#pragma unroll
            for (int j = 0; j < 4; j++)
                acc[i][j] = fmaf(a[i], bb[j], acc[i][j]);
    }
    float* out = scores + ((size_t)bh * S_ + q0) * S_ + k0;
#pragma unroll
    for (int i = 0; i < 4; i++)
#pragma unroll
        for (int j = 0; j < 4; j++)
            out[(size_t)(ty * 4 + i) * S_ + tx * 4 + j] = acc[i][j];
}

// ---------------- masked softmax over rows of 512 ---------------------------
__global__ __launch_bounds__(128) void softmax_kernel(
    float* __restrict__ scores, const void* __restrict__ maskp)
{
    int row = blockIdx.x;       // bh*S + qi
    int bh  = row >> 9;
    int b   = bh >> 4;
    float* p = scores + (size_t)row * S_;
    int mode = g_mask_mode;
    const unsigned char* mu8 = (const unsigned char*)maskp;
    const int*   mi = (const int*)maskp;
    const float* mf = (const float*)maskp;
    int tid = threadIdx.x;
    float v[4];
    float mx = -1e30f;
#pragma unroll
    for (int kq = 0; kq < 4; kq++) {
        int j = tid + kq * 128;
        float s = p[j] * 0.125f;   // 1/sqrt(64)
        bool m;
        if (mode == 1)      m = mi[b * S_ + j] != 0;
        else if (mode == 2) m = mf[b * S_ + j] != 0.f;
        else                m = mu8[b * S_ + j] != 0;
        v[kq] = m ? -1e30f : s;
        mx = fmaxf(mx, v[kq]);
    }
    __shared__ float red[128];
    red[tid] = mx; __syncthreads();
    for (int off = 64; off > 0; off >>= 1) {
        if (tid < off) red[tid] = fmaxf(red[tid], red[tid + off]);
        __syncthreads();
    }
    mx = red[0]; __syncthreads();
    float sum = 0.f;
#pragma unroll
    for (int kq = 0; kq < 4; kq++) { v[kq] = expf(v[kq] - mx); sum += v[kq]; }
    red[tid] = sum; __syncthreads();
    for (int off = 64; off > 0; off >>= 1) {
        if (tid < off) red[tid] += red[tid + off];
        __syncthreads();
    }
    float inv = 1.f / red[0];
#pragma unroll
    for (int kq = 0; kq < 4; kq++) p[tid + kq * 128] = v[kq] * inv;
}

// ---------------- attn = probs @ V (per b,h), written back to [S,B,D] -------
__global__ __launch_bounds__(256) void attnv_kernel(
    const float* __restrict__ probs, const float* __restrict__ v,
    float* __restrict__ attn)
{
    int bh = blockIdx.y;
    int b = bh >> 4, h = bh & 15;
    int q0 = blockIdx.x << 6;
    __shared__ float Ps[64][33];
    __shared__ float Vs[32][64];
    int tid = threadIdx.x;
    int tx = tid & 15, ty = tid >> 4;
    float acc[4][4] = {};
    const float* pb = probs + ((size_t)bh * S_ + q0) * S_;
    const float* vb = v + (size_t)b * D_ + h * HD_;
    for (int kt = 0; kt < S_; kt += 32) {
#pragma unroll
        for (int it = 0; it < 2; it++) {
            int e = tid + it * 256;
            int r = e >> 3, c = (e & 7) << 2;
            float4 pv = *(const float4*)(pb + (size_t)r * S_ + kt + c);
            Ps[r][c] = pv.x; Ps[r][c + 1] = pv.y; Ps[r][c + 2] = pv.z; Ps[r][c + 3] = pv.w;
            int r2 = e >> 4, c2 = (e & 15) << 2;
            *(float4*)(&Vs[r2][c2]) = *(const float4*)(vb + (size_t)(kt + r2) * (B_ * D_) + c2);
        }
        __syncthreads();
#pragma unroll
        for (int kk = 0; kk < 32; kk++) {
            float a[4];
#pragma unroll
            for (int i = 0; i < 4; i++) a[i] = Ps[ty * 4 + i][kk];
            float4 bv4 = *(const float4*)(&Vs[kk][tx * 4]);
            float bb[4] = { bv4.x, bv4.y, bv4.z, bv4.w };
#pragma unroll
            for (int i = 0; i < 4; i++)
#pragma unroll
                for (int j = 0; j < 4; j++)
                    acc[i][j] = fmaf(a[i], bb[j], acc[i][j]);
        }
        __syncthreads();
    }
#pragma unroll
    for (int i = 0; i < 4; i++) {
        int qi = q0 + ty * 4 + i;
#pragma unroll
        for (int j = 0; j < 4; j++)
            attn[((size_t)qi * B_ + b) * D_ + h * HD_ + tx * 4 + j] = acc[i][j];
    }
}

// ---------------- host orchestration ---------------------------------------
extern "C" void kernel_launch(void* const* d_in, const int* in_sizes, int n_in,
                              void* d_out, int out_size)
{
    (void)in_sizes; (void)n_in; (void)out_size;
    const float* segments  = (const float*)d_in[0];
    const float* durations = (const float*)d_in[1];
    const void*  mask      = d_in[2];
    const float* Wproj = (const float*)d_in[3];
    const float* bproj = (const float*)d_in[4];
    const float* Wdur  = (const float*)d_in[5];
    const float* bdur  = (const float*)d_in[6];
    const float* ln1g  = (const float*)d_in[7];
    const float* ln1b  = (const float*)d_in[8];
    const float* Wq    = (const float*)d_in[9];
    const float* bq    = (const float*)d_in[10];
    const float* Wk    = (const float*)d_in[11];
    const float* bk    = (const float*)d_in[12];
    const float* Wv    = (const float*)d_in[13];
    const float* bv    = (const float*)d_in[14];
    const float* Wo    = (const float*)d_in[15];
    const float* bo    = (const float*)d_in[16];
    const float* ln2g  = (const float*)d_in[17];
    const float* ln2b  = (const float*)d_in[18];
    const float* W1    = (const float*)d_in[19];
    const float* b1    = (const float*)d_in[20];
    const float* W2    = (const float*)d_in[21];
    const float* b2    = (const float*)d_in[22];
    float* x = (float*)d_out;

    float *h, *q, *kb, *vb, *attn, *ff, *scores;
    cudaGetSymbolAddress((void**)&h,      g_h);
    cudaGetSymbolAddress((void**)&q,      g_q);
    cudaGetSymbolAddress((void**)&kb,     g_k);
    cudaGetSymbolAddress((void**)&vb,     g_v);
    cudaGetSymbolAddress((void**)&attn,   g_attn);
    cudaGetSymbolAddress((void**)&ff,     g_ff);
    cudaGetSymbolAddress((void**)&scores, g_scores);

    detect_mask_kernel<<<1, 512>>>(mask);

    dim3 gD(D_ / 128, SB_ / 128);   // (8,16)
    dim3 gF(F_ / 128, SB_ / 128);   // (32,16)

    // input projection: x = segments @ Wproj + bproj; then += dur*Wdur + bdur
    gemm_kernel<0><<<gD, 256>>>(segments, Wproj, bproj, x, SB_, D_, DIN_);
    adddur_kernel<<<(SB_ * D_) / 256, 256>>>(x, durations, Wdur, bdur);

    const size_t DD = (size_t)D_ * D_;
    const size_t DF = (size_t)D_ * F_;
    for (int l = 0; l < L_; l++) {
        ln_kernel<<<SB_, 256>>>(x, ln1g + (size_t)l * D_, ln1b + (size_t)l * D_, h);
        gemm_kernel<0><<<gD, 256>>>(h, Wq + l * DD, bq + (size_t)l * D_, q,  SB_, D_, D_);
        gemm_kernel<0><<<gD, 256>>>(h, Wk + l * DD, bk + (size_t)l * D_, kb, SB_, D_, D_);
        gemm_kernel<0><<<gD, 256>>>(h, Wv + l * DD, bv + (size_t)l * D_, vb, SB_, D_, D_);
        rope_kernel<<<(SB_ * H_ * 32) / 256, 256>>>(q);
        rope_kernel<<<(SB_ * H_ * 32) / 256, 256>>>(kb);
        scores_kernel<<<dim3(8, 8, BH_), 256>>>(q, kb, scores);
        softmax_kernel<<<BH_ * S_, 128>>>(scores, mask);
        attnv_kernel<<<dim3(8, BH_), 256>>>(scores, vb, attn);
        gemm_kernel<1><<<gD, 256>>>(attn, Wo + l * DD, bo + (size_t)l * D_, x, SB_, D_, D_);
        ln_kernel<<<SB_, 256>>>(x, ln2g + (size_t)l * D_, ln2b + (size_t)l * D_, h);
        gemm_kernel<2><<<gF, 256>>>(h,  W1 + l * DF, b1 + (size_t)l * F_, ff, SB_, F_, D_);
        gemm_kernel<1><<<gD, 256>>>(ff, W2 + l * DF, b2 + (size_t)l * D_, x,  SB_, D_, F_);
    }
}

// round 3
// speedup vs baseline: 1.8839x; 1.8839x over previous
#include <cuda_runtime.h>
#include <cuda_bf16.h>
#include <math.h>
#include <stdint.h>

#define L_   12
#define S_   512
#define B_   4
#define DIN_ 768
#define D_   1024
#define H_   16
#define F_   4096
#define HD_  64
#define SB_  2048        // S*B rows
#define BH_  (B_*H_)

// ---------------- scratch (device globals: allocation-free) ----------------
__device__ float g_h   [SB_*D_];
__device__ float g_q   [SB_*D_];
__device__ float g_k   [SB_*D_];
__device__ float g_v   [SB_*D_];
__device__ float g_attn[SB_*D_];
__device__ float g_ff  [(size_t)SB_*F_];
__device__ float g_scores[(size_t)BH_*S_*S_];
__device__ int   g_mask_mode;

// ============================================================================
// helpers
// ============================================================================
__device__ __forceinline__ uint32_t smem_u32(const void* p) {
    uint32_t a;
    asm("{ .reg .u64 t; cvta.to.shared.u64 t, %1; cvt.u32.u64 %0, t; }"
        : "=r"(a) : "l"(p));
    return a;
}

__device__ __forceinline__ void ldsm4(uint32_t* r, uint32_t addr) {
    asm volatile("ldmatrix.sync.aligned.m8n8.x4.shared.b16 {%0,%1,%2,%3}, [%4];"
                 : "=r"(r[0]), "=r"(r[1]), "=r"(r[2]), "=r"(r[3]) : "r"(addr));
}
__device__ __forceinline__ void ldsm4t(uint32_t* r, uint32_t addr) {
    asm volatile("ldmatrix.sync.aligned.m8n8.x4.trans.shared.b16 {%0,%1,%2,%3}, [%4];"
                 : "=r"(r[0]), "=r"(r[1]), "=r"(r[2]), "=r"(r[3]) : "r"(addr));
}
__device__ __forceinline__ void mma16816(float* d, const uint32_t* a, const uint32_t* b) {
    asm volatile(
        "mma.sync.aligned.m16n8k16.row.col.f32.bf16.bf16.f32 "
        "{%0,%1,%2,%3}, {%4,%5,%6,%7}, {%8,%9}, {%0,%1,%2,%3};"
        : "+f"(d[0]), "+f"(d[1]), "+f"(d[2]), "+f"(d[3])
        : "r"(a[0]), "r"(a[1]), "r"(a[2]), "r"(a[3]), "r"(b[0]), "r"(b[1]));
}

// fp32 -> bf16 hi + bf16 lo (packed pairs)
__device__ __forceinline__ uint32_t packhl(float a, float b, uint32_t& lo) {
    __nv_bfloat162 h = __floats2bfloat162_rn(a, b);
    float ra = a - __bfloat162float(h.x);
    float rb = b - __bfloat162float(h.y);
    __nv_bfloat162 l = __floats2bfloat162_rn(ra, rb);
    lo = *(uint32_t*)&l;
    return *(uint32_t*)&h;
}

// ============================================================================
// mma.sync split-bf16 GEMM: C[M,N] = A[M,K] @ W[K,N]  (+bias, epilogue MODE)
// CTA tile 128x128, BK=32, double-buffered smem, 8 warps (warp tile 32x64).
// MODE 0: C = acc+bias   MODE 1: C += acc+bias   MODE 2: C = gelu(acc+bias)
// ============================================================================
// smem stage layout (bytes):
//   AH [128][40 bf16]  = 10240     (row stride 80B)
//   AL                 @ +10240
//   BH [32][136 bf16]  =  8704     (row stride 272B)
//   BL                 @ +29184
#define A_STRIDE   80
#define B_STRIDE   272
#define AH_OFF     0
#define AL_OFF     10240
#define BH_OFF     20480
#define BL_OFF     29184
#define STAGE_B    37888
#define GEMM_SMEM  (2*STAGE_B)

__device__ __forceinline__ void load_tiles(
    const float* __restrict__ A, const float* __restrict__ W,
    int K, int N, int rowBase, int colBase, int ck, char* stage, int tid)
{
    // ---- A tile [128 rows x 32 k] ----
    {
        const int row = tid >> 1;
        const int kh  = (tid & 1) << 4;
        const float* ap = A + (size_t)(rowBase + row) * K + ck + kh;
        char* aH = stage + AH_OFF;
        char* aL = stage + AL_OFF;
#pragma unroll
        for (int i = 0; i < 4; i++) {
            float4 v = *(const float4*)(ap + i * 4);
            uint32_t l01, l23;
            uint32_t h01 = packhl(v.x, v.y, l01);
            uint32_t h23 = packhl(v.z, v.w, l23);
            uint32_t off = (uint32_t)(row * A_STRIDE + (kh + i * 4) * 2);
            *(uint2*)(aH + off) = make_uint2(h01, h23);
            *(uint2*)(aL + off) = make_uint2(l01, l23);
        }
    }
    // ---- B tile [32 k x 128 n], kept row-major (k-major rows) ----
    {
        const int k  = tid >> 3;
        const int n0 = (tid & 7) << 4;
        const float* wp = W + (size_t)(ck + k) * N + colBase + n0;
        char* bH = stage + BH_OFF;
        char* bL = stage + BL_OFF;
#pragma unroll
        for (int i = 0; i < 4; i++) {
            float4 v = *(const float4*)(wp + i * 4);
            uint32_t l01, l23;
            uint32_t h01 = packhl(v.x, v.y, l01);
            uint32_t h23 = packhl(v.z, v.w, l23);
            uint32_t off = (uint32_t)(k * B_STRIDE + (n0 + i * 4) * 2);
            *(uint2*)(bH + off) = make_uint2(h01, h23);
            *(uint2*)(bL + off) = make_uint2(l01, l23);
        }
    }
}

template<int MODE>
__global__ void __launch_bounds__(256) hmma_gemm(
    const float* __restrict__ A, const float* __restrict__ W,
    const float* __restrict__ bias, float* __restrict__ C,
    int M, int N, int K)
{
    extern __shared__ char smem[];
    const int tid  = threadIdx.x;
    const int lane = tid & 31;
    const int wid  = tid >> 5;
    const int m0   = (wid & 3) << 5;   // warp row offset in CTA tile
    const int n0w  = (wid >> 2) << 6;  // warp col offset

    const int rowBase = blockIdx.y << 7;
    const int colBase = blockIdx.x << 7;
    const int NC = K >> 5;

    float acc[2][8][4];
#pragma unroll
    for (int a = 0; a < 2; a++)
#pragma unroll
        for (int b = 0; b < 8; b++)
#pragma unroll
            for (int c = 0; c < 4; c++) acc[a][b][c] = 0.f;

    load_tiles(A, W, K, N, rowBase, colBase, 0, smem, tid);
    __syncthreads();

    for (int c = 0; c < NC; c++) {
        char* cur = smem + (c & 1) * STAGE_B;
        if (c + 1 < NC)
            load_tiles(A, W, K, N, rowBase, colBase, (c + 1) << 5,
                       smem + ((c + 1) & 1) * STAGE_B, tid);

        uint32_t aHu = smem_u32(cur);
        const int arow = lane & 15;
        const int aoff = (lane >> 4) << 4;

#pragma unroll
        for (int ks = 0; ks < 32; ks += 16) {
            uint32_t ah[2][4], al[2][4];
#pragma unroll
            for (int mt = 0; mt < 2; mt++) {
                uint32_t ad = aHu + (uint32_t)((m0 + mt * 16 + arow) * A_STRIDE + ks * 2 + aoff);
                ldsm4(ah[mt], ad);
                ldsm4(al[mt], ad + AL_OFF);
            }
            uint32_t bh[4][4], bl[4][4];
#pragma unroll
            for (int np = 0; np < 4; np++) {
                uint32_t bd = aHu + BH_OFF +
                    (uint32_t)((ks + arow) * B_STRIDE + ((n0w + np * 16) << 1) + aoff);
                ldsm4t(bh[np], bd);
                ldsm4t(bl[np], bd + (BL_OFF - BH_OFF));
            }
#pragma unroll
            for (int mt = 0; mt < 2; mt++)
#pragma unroll
                for (int np = 0; np < 4; np++)
#pragma unroll
                    for (int e = 0; e < 2; e++) {
                        uint32_t bfh[2] = { bh[np][2 * e], bh[np][2 * e + 1] };
                        uint32_t bfl[2] = { bl[np][2 * e], bl[np][2 * e + 1] };
                        float* d = acc[mt][np * 2 + e];
                        mma16816(d, ah[mt], bfh);
                        mma16816(d, al[mt], bfh);
                        mma16816(d, ah[mt], bfl);
                    }
        }
        __syncthreads();
    }

    // ---- epilogue ----
#pragma unroll
    for (int mt = 0; mt < 2; mt++) {
        const int r0 = rowBase + m0 + mt * 16 + (lane >> 2);
#pragma unroll
        for (int nt = 0; nt < 8; nt++) {
            const int c0 = colBase + n0w + nt * 8 + ((lane & 3) << 1);
            float* d = acc[mt][nt];
            float b0 = bias[c0], b1 = bias[c0 + 1];
#pragma unroll
            for (int half = 0; half < 2; half++) {
                const int row = r0 + half * 8;
                float v0 = d[half * 2 + 0] + b0;
                float v1 = d[half * 2 + 1] + b1;
                float* out = C + (size_t)row * N + c0;
                if (MODE == 0) { out[0] = v0; out[1] = v1; }
                else if (MODE == 1) { out[0] += v0; out[1] += v1; }
                else {
                    out[0] = 0.5f * v0 * (1.f + erff(v0 * 0.70710678118654752f));
                    out[1] = 0.5f * v1 * (1.f + erff(v1 * 0.70710678118654752f));
                }
            }
        }
    }
}

// ---------------- mask dtype detection (reads exactly 2048 bytes) ----------
__global__ void detect_mask_kernel(const void* m) {
    __shared__ int flags[2];
    if (threadIdx.x == 0) { flags[0] = 0; flags[1] = 0; }
    __syncthreads();
    unsigned v = ((const unsigned*)m)[threadIdx.x];
    if (v > 1u) flags[0] = 1;
    if (v != 0u && v != 0x3F800000u) flags[1] = 1;
    __syncthreads();
    if (threadIdx.x == 0)
        g_mask_mode = (!flags[0]) ? 1 : ((!flags[1]) ? 2 : 0);
}

// ---------------- LayerNorm ----------------
__global__ __launch_bounds__(256) void ln_kernel(
    const float* __restrict__ x, const float* __restrict__ g,
    const float* __restrict__ b, float* __restrict__ out)
{
    int row = blockIdx.x;
    int tid = threadIdx.x;
    const float* xr = x + (size_t)row * D_;
    float4 v = *(const float4*)(xr + tid * 4);
    float s  = v.x + v.y + v.z + v.w;
    float s2 = v.x * v.x + v.y * v.y + v.z * v.z + v.w * v.w;
    __shared__ float r1[256], r2[256];
    r1[tid] = s; r2[tid] = s2;
    __syncthreads();
    for (int off = 128; off > 0; off >>= 1) {
        if (tid < off) { r1[tid] += r1[tid + off]; r2[tid] += r2[tid + off]; }
        __syncthreads();
    }
    float mean = r1[0] * (1.f / D_);
    float var  = r2[0] * (1.f / D_) - mean * mean;
    float rstd = rsqrtf(var + 1e-5f);
    float4 gv = *(const float4*)(g + tid * 4);
    float4 bv = *(const float4*)(b + tid * 4);
    float4 o;
    o.x = (v.x - mean) * rstd * gv.x + bv.x;
    o.y = (v.y - mean) * rstd * gv.y + bv.y;
    o.z = (v.z - mean) * rstd * gv.z + bv.z;
    o.w = (v.w - mean) * rstd * gv.w + bv.w;
    *(float4*)(out + (size_t)row * D_ + tid * 4) = o;
}

// ---------------- RoPE in place ----------------
__global__ void rope_kernel(float* __restrict__ q) {
    int idx = blockIdx.x * blockDim.x + threadIdx.x;
    int i = idx & 31;
    int h = (idx >> 5) & (H_ - 1);
    int r = idx >> 9;
    int s = r >> 2;
    float inv = expf(-0.28782313662425572f * (float)i);
    float ang = (float)s * inv;
    float c, sn;
    sincosf(ang, &sn, &c);
    float* base = q + (size_t)r * D_ + h * HD_ + i;
    float x1 = base[0], x2 = base[32];
    base[0]  = x1 * c - x2 * sn;
    base[32] = x2 * c + x1 * sn;
}

// ---------------- x += dur[r]*Wdur[c] + bdur[c] ----------------
__global__ void adddur_kernel(float* __restrict__ x, const float* __restrict__ dur,
                              const float* __restrict__ wd, const float* __restrict__ bd) {
    int idx = blockIdx.x * blockDim.x + threadIdx.x;
    int r = idx >> 10, c = idx & 1023;
    x[idx] += dur[r] * wd[c] + bd[c];
}

// ---------------- scores = q @ k^T (per b,h) ----------------
__global__ __launch_bounds__(256) void scores_kernel(
    const float* __restrict__ q, const float* __restrict__ k,
    float* __restrict__ scores)
{
    int bh = blockIdx.z;
    int b = bh >> 4, h = bh & 15;
    int q0 = blockIdx.y << 6, k0 = blockIdx.x << 6;
    __shared__ float Qs[64][65], Ks[64][65];
    int tid = threadIdx.x;
    const float* qb = q + (size_t)b * D_ + h * HD_;
    const float* kb = k + (size_t)b * D_ + h * HD_;
#pragma unroll
    for (int it = 0; it < 4; it++) {
        int e = tid + it * 256;
        int r = e >> 4, c = (e & 15) << 2;
        float4 v = *(const float4*)(qb + (size_t)(q0 + r) * (B_ * D_) + c);
        Qs[r][c] = v.x; Qs[r][c + 1] = v.y; Qs[r][c + 2] = v.z; Qs[r][c + 3] = v.w;
        float4 w = *(const float4*)(kb + (size_t)(k0 + r) * (B_ * D_) + c);
        Ks[r][c] = w.x; Ks[r][c + 1] = w.y; Ks[r][c + 2] = w.z; Ks[r][c + 3] = w.w;
    }
    __syncthreads();
    int tx = tid & 15, ty = tid >> 4;
    float acc[4][4] = {};
#pragma unroll 16
    for (int d = 0; d < 64; d++) {
        float a[4], bb[4];
#pragma unroll
        for (int i = 0; i < 4; i++) a[i]  = Qs[ty * 4 + i][d];
#pragma unroll
        for (int j = 0; j < 4; j++) bb[j] = Ks[tx * 4 + j][d];
#pragma unroll
        for (int i = 0; i < 4; i++)
#pragma unroll
            for (int j = 0; j < 4; j++)
                acc[i][j] = fmaf(a[i], bb[j], acc[i][j]);
    }
    float* out = scores + ((size_t)bh * S_ + q0) * S_ + k0;
#pragma unroll
    for (int i = 0; i < 4; i++)
#pragma unroll
        for (int j = 0; j < 4; j++)
            out[(size_t)(ty * 4 + i) * S_ + tx * 4 + j] = acc[i][j];
}

// ---------------- masked softmax ----------------
__global__ __launch_bounds__(128) void softmax_kernel(
    float* __restrict__ scores, const void* __restrict__ maskp)
{
    int row = blockIdx.x;
    int bh  = row >> 9;
    int b   = bh >> 4;
    float* p = scores + (size_t)row * S_;
    int mode = g_mask_mode;
    const unsigned char* mu8 = (const unsigned char*)maskp;
    const int*   mi = (const int*)maskp;
    const float* mf = (const float*)maskp;
    int tid = threadIdx.x;
    float v[4];
    float mx = -1e30f;
#pragma unroll
    for (int kq = 0; kq < 4; kq++) {
        int j = tid + kq * 128;
        float s = p[j] * 0.125f;
        bool m;
        if (mode == 1)      m = mi[b * S_ + j] != 0;
        else if (mode == 2) m = mf[b * S_ + j] != 0.f;
        else                m = mu8[b * S_ + j] != 0;
        v[kq] = m ? -1e30f : s;
        mx = fmaxf(mx, v[kq]);
    }
    __shared__ float red[128];
    red[tid] = mx; __syncthreads();
    for (int off = 64; off > 0; off >>= 1) {
        if (tid < off) red[tid] = fmaxf(red[tid], red[tid + off]);
        __syncthreads();
    }
    mx = red[0]; __syncthreads();
    float sum = 0.f;
#pragma unroll
    for (int kq = 0; kq < 4; kq++) { v[kq] = expf(v[kq] - mx); sum += v[kq]; }
    red[tid] = sum; __syncthreads();
    for (int off = 64; off > 0; off >>= 1) {
        if (tid < off) red[tid] += red[tid + off];
        __syncthreads();
    }
    float inv = 1.f / red[0];
#pragma unroll
    for (int kq = 0; kq < 4; kq++) p[tid + kq * 128] = v[kq] * inv;
}

// ---------------- attn = probs @ V ----------------
__global__ __launch_bounds__(256) void attnv_kernel(
    const float* __restrict__ probs, const float* __restrict__ v,
    float* __restrict__ attn)
{
    int bh = blockIdx.y;
    int b = bh >> 4, h = bh & 15;
    int q0 = blockIdx.x << 6;
    __shared__ float Ps[64][33];
    __shared__ float Vs[32][64];
    int tid = threadIdx.x;
    int tx = tid & 15, ty = tid >> 4;
    float acc[4][4] = {};
    const float* pb = probs + ((size_t)bh * S_ + q0) * S_;
    const float* vb = v + (size_t)b * D_ + h * HD_;
    for (int kt = 0; kt < S_; kt += 32) {
#pragma unroll
        for (int it = 0; it < 2; it++) {
            int e = tid + it * 256;
            int r = e >> 3, c = (e & 7) << 2;
            float4 pv = *(const float4*)(pb + (size_t)r * S_ + kt + c);
            Ps[r][c] = pv.x; Ps[r][c + 1] = pv.y; Ps[r][c + 2] = pv.z; Ps[r][c + 3] = pv.w;
            int r2 = e >> 4, c2 = (e & 15) << 2;
            *(float4*)(&Vs[r2][c2]) = *(const float4*)(vb + (size_t)(kt + r2) * (B_ * D_) + c2);
        }
        __syncthreads();
#pragma unroll
        for (int kk = 0; kk < 32; kk++) {
            float a[4];
#pragma unroll
            for (int i = 0; i < 4; i++) a[i] = Ps[ty * 4 + i][kk];
            float4 bv4 = *(const float4*)(&Vs[kk][tx * 4]);
            float bb[4] = { bv4.x, bv4.y, bv4.z, bv4.w };
#pragma unroll
            for (int i = 0; i < 4; i++)
#pragma unroll
                for (int j = 0; j < 4; j++)
                    acc[i][j] = fmaf(a[i], bb[j], acc[i][j]);
        }
        __syncthreads();
    }
#pragma unroll
    for (int i = 0; i < 4; i++) {
        int qi = q0 + ty * 4 + i;
#pragma unroll
        for (int j = 0; j < 4; j++)
            attn[((size_t)qi * B_ + b) * D_ + h * HD_ + tx * 4 + j] = acc[i][j];
    }
}

// ---------------- host orchestration ----------------
extern "C" void kernel_launch(void* const* d_in, const int* in_sizes, int n_in,
                              void* d_out, int out_size)
{
    (void)in_sizes; (void)n_in; (void)out_size;
    const float* segments  = (const float*)d_in[0];
    const float* durations = (const float*)d_in[1];
    const void*  mask      = d_in[2];
    const float* Wproj = (const float*)d_in[3];
    const float* bproj = (const float*)d_in[4];
    const float* Wdur  = (const float*)d_in[5];
    const float* bdur  = (const float*)d_in[6];
    const float* ln1g  = (const float*)d_in[7];
    const float* ln1b  = (const float*)d_in[8];
    const float* Wq    = (const float*)d_in[9];
    const float* bq    = (const float*)d_in[10];
    const float* Wk    = (const float*)d_in[11];
    const float* bk    = (const float*)d_in[12];
    const float* Wv    = (const float*)d_in[13];
    const float* bv    = (const float*)d_in[14];
    const float* Wo    = (const float*)d_in[15];
    const float* bo    = (const float*)d_in[16];
    const float* ln2g  = (const float*)d_in[17];
    const float* ln2b  = (const float*)d_in[18];
    const float* W1    = (const float*)d_in[19];
    const float* b1    = (const float*)d_in[20];
    const float* W2    = (const float*)d_in[21];
    const float* b2    = (const float*)d_in[22];
    float* x = (float*)d_out;

    float *h, *q, *kb, *vb, *attn, *ff, *scores;
    cudaGetSymbolAddress((void**)&h,      g_h);
    cudaGetSymbolAddress((void**)&q,      g_q);
    cudaGetSymbolAddress((void**)&kb,     g_k);
    cudaGetSymbolAddress((void**)&vb,     g_v);
    cudaGetSymbolAddress((void**)&attn,   g_attn);
    cudaGetSymbolAddress((void**)&ff,     g_ff);
    cudaGetSymbolAddress((void**)&scores, g_scores);

    cudaFuncSetAttribute(hmma_gemm<0>, cudaFuncAttributeMaxDynamicSharedMemorySize, GEMM_SMEM);
    cudaFuncSetAttribute(hmma_gemm<1>, cudaFuncAttributeMaxDynamicSharedMemorySize, GEMM_SMEM);
    cudaFuncSetAttribute(hmma_gemm<2>, cudaFuncAttributeMaxDynamicSharedMemorySize, GEMM_SMEM);

    detect_mask_kernel<<<1, 512>>>(mask);

    dim3 gD(D_ / 128, SB_ / 128);   // (8,16)
    dim3 gF(F_ / 128, SB_ / 128);   // (32,16)

    hmma_gemm<0><<<gD, 256, GEMM_SMEM>>>(segments, Wproj, bproj, x, SB_, D_, DIN_);
    adddur_kernel<<<(SB_ * D_) / 256, 256>>>(x, durations, Wdur, bdur);

    const size_t DD = (size_t)D_ * D_;
    const size_t DF = (size_t)D_ * F_;
    for (int l = 0; l < L_; l++) {
        ln_kernel<<<SB_, 256>>>(x, ln1g + (size_t)l * D_, ln1b + (size_t)l * D_, h);
        hmma_gemm<0><<<gD, 256, GEMM_SMEM>>>(h, Wq + l * DD, bq + (size_t)l * D_, q,  SB_, D_, D_);
        hmma_gemm<0><<<gD, 256, GEMM_SMEM>>>(h, Wk + l * DD, bk + (size_t)l * D_, kb, SB_, D_, D_);
        hmma_gemm<0><<<gD, 256, GEMM_SMEM>>>(h, Wv + l * DD, bv + (size_t)l * D_, vb, SB_, D_, D_);
        rope_kernel<<<(SB_ * H_ * 32) / 256, 256>>>(q);
        rope_kernel<<<(SB_ * H_ * 32) / 256, 256>>>(kb);
        scores_kernel<<<dim3(8, 8, BH_), 256>>>(q, kb, scores);
        softmax_kernel<<<BH_ * S_, 128>>>(scores, mask);
        attnv_kernel<<<dim3(8, BH_), 256>>>(scores, vb, attn);
        hmma_gemm<1><<<gD, 256, GEMM_SMEM>>>(attn, Wo + l * DD, bo + (size_t)l * D_, x, SB_, D_, D_);
        ln_kernel<<<SB_, 256>>>(x, ln2g + (size_t)l * D_, ln2b + (size_t)l * D_, h);
        hmma_gemm<2><<<gF, 256, GEMM_SMEM>>>(h,  W1 + l * DF, b1 + (size_t)l * F_, ff, SB_, F_, D_);
        hmma_gemm<1><<<gD, 256, GEMM_SMEM>>>(ff, W2 + l * DF, b2 + (size_t)l * D_, x,  SB_, D_, F_);
    }
}

// round 5
// speedup vs baseline: 2.3861x; 1.2666x over previous
#include <cuda_runtime.h>
#include <cuda_bf16.h>
#include <math.h>
#include <stdint.h>

#define L_   12
#define S_   512
#define B_   4
#define DIN_ 768
#define D_   1024
#define H_   16
#define F_   4096
#define HD_  64
#define SB_  2048
#define BH_  (B_*H_)
#define DD_  (D_*D_)
#define DF_  (D_*F_)

typedef __nv_bfloat16 bf16;

// ---------------- persistent scratch (device globals) ----------------
__device__ __align__(16) bf16 g_wqkv_h[(size_t)L_*3*DD_];
__device__ __align__(16) bf16 g_wqkv_l[(size_t)L_*3*DD_];
__device__ __align__(16) bf16 g_wo_h  [(size_t)L_*DD_];
__device__ __align__(16) bf16 g_wo_l  [(size_t)L_*DD_];
__device__ __align__(16) bf16 g_w1_h  [(size_t)L_*DF_];
__device__ __align__(16) bf16 g_w1_l  [(size_t)L_*DF_];
__device__ __align__(16) bf16 g_w2_h  [(size_t)L_*DF_];
__device__ __align__(16) bf16 g_w2_l  [(size_t)L_*DF_];
__device__ __align__(16) bf16 g_wp_h  [DIN_*D_];
__device__ __align__(16) bf16 g_wp_l  [DIN_*D_];
__device__ float g_bqkv[L_*3*D_];
__device__ __align__(16) bf16 g_seg_h[SB_*DIN_];
__device__ __align__(16) bf16 g_seg_l[SB_*DIN_];
__device__ __align__(16) bf16 g_hh[SB_*D_];
__device__ __align__(16) bf16 g_hl[SB_*D_];
__device__ __align__(16) bf16 g_ah[SB_*D_];
__device__ __align__(16) bf16 g_al[SB_*D_];
__device__ __align__(16) bf16 g_ffh[(size_t)SB_*F_];
__device__ __align__(16) bf16 g_ffl[(size_t)SB_*F_];
__device__ float g_qkv[3*SB_*D_];
__device__ float g_scores[(size_t)BH_*S_*S_];
__device__ int   g_mask_mode;

// ============================================================================
// helpers
// ============================================================================
__device__ __forceinline__ uint32_t smem_u32(const void* p) {
    uint32_t a;
    asm("{ .reg .u64 t; cvta.to.shared.u64 t, %1; cvt.u32.u64 %0, t; }"
        : "=r"(a) : "l"(p));
    return a;
}
__device__ __forceinline__ void ldsm4(uint32_t* r, uint32_t addr) {
    asm volatile("ldmatrix.sync.aligned.m8n8.x4.shared.b16 {%0,%1,%2,%3}, [%4];"
                 : "=r"(r[0]), "=r"(r[1]), "=r"(r[2]), "=r"(r[3]) : "r"(addr));
}
__device__ __forceinline__ void ldsm4t(uint32_t* r, uint32_t addr) {
    asm volatile("ldmatrix.sync.aligned.m8n8.x4.trans.shared.b16 {%0,%1,%2,%3}, [%4];"
                 : "=r"(r[0]), "=r"(r[1]), "=r"(r[2]), "=r"(r[3]) : "r"(addr));
}
__device__ __forceinline__ void mma16816(float* d, const uint32_t* a, const uint32_t* b) {
    asm volatile(
        "mma.sync.aligned.m16n8k16.row.col.f32.bf16.bf16.f32 "
        "{%0,%1,%2,%3}, {%4,%5,%6,%7}, {%8,%9}, {%0,%1,%2,%3};"
        : "+f"(d[0]), "+f"(d[1]), "+f"(d[2]), "+f"(d[3])
        : "r"(a[0]), "r"(a[1]), "r"(a[2]), "r"(a[3]), "r"(b[0]), "r"(b[1]));
}
#define CP_ASYNC(dst, src) \
    asm volatile("cp.async.cg.shared.global [%0], [%1], 16;" :: "r"(dst), "l"(src))
#define CP_COMMIT() asm volatile("cp.async.commit_group;")
#define CP_WAIT(n)  asm volatile("cp.async.wait_group %0;" :: "n"(n))

__device__ __forceinline__ void split2(float v0, float v1, uint32_t& hi, uint32_t& lo) {
    __nv_bfloat162 h = __floats2bfloat162_rn(v0, v1);
    __nv_bfloat162 l = __floats2bfloat162_rn(v0 - __bfloat162float(h.x),
                                             v1 - __bfloat162float(h.y));
    hi = *(uint32_t*)&h; lo = *(uint32_t*)&l;
}

// ============================================================================
// weight/activation split conversion: dst[(i/inner)*inner*gm + go*inner + i%inner]
// ============================================================================
__global__ void conv_split(const float* __restrict__ src, bf16* __restrict__ dh,
                           bf16* __restrict__ dl, int n, int inner, int gm, int go) {
    int i = blockIdx.x * blockDim.x + threadIdx.x;
    if (i >= n) return;
    float v = src[i];
    bf16 h = __float2bfloat16(v);
    float r = v - __bfloat162float(h);
    size_t d = (size_t)(i / inner) * inner * gm + (size_t)go * inner + (i % inner);
    dh[d] = h; dl[d] = __float2bfloat16(r);
}
__global__ void map_bias(const float* __restrict__ src, float* __restrict__ dst,
                         int n, int inner, int gm, int go) {
    int i = blockIdx.x * blockDim.x + threadIdx.x;
    if (i >= n) return;
    dst[(size_t)(i / inner) * inner * gm + (size_t)go * inner + (i % inner)] = src[i];
}

// ============================================================================
// split-bf16 HMMA GEMM v2: pre-split operands, cp.async pipeline.
// C[M,N] (+z) = A[M,K] @ W[K,N]  (3-term split accumulate)
// MODE 0: C = acc+bias   MODE 1: C += acc+bias   MODE 2: CH/CL = split(gelu(acc+bias))
// ============================================================================
#define A_STRIDE   80
#define B_STRIDE   272
#define AH_OFF     0
#define AL_OFF     10240
#define BH_OFF     20480
#define BL_OFF     29184
#define STAGE_B    37888
#define GEMM_SMEM  (2*STAGE_B)

__device__ __forceinline__ void load_stage(
    const bf16* __restrict__ AH, const bf16* __restrict__ AL,
    const bf16* __restrict__ WH, const bf16* __restrict__ WL,
    int K, int N, int rowBase, int colBase, int ck, uint32_t st, int tid)
{
#pragma unroll
    for (int t = 0; t < 4; t++) {
        int idx = tid + t * 256;
        int tile = idx >> 9;
        int r = (idx >> 2) & 127;
        int c16 = idx & 3;
        const bf16* src = (tile ? AL : AH) + (size_t)(rowBase + r) * K + ck + c16 * 8;
        uint32_t dst = st + (tile ? AL_OFF : AH_OFF) + r * A_STRIDE + c16 * 16;
        CP_ASYNC(dst, src);
    }
#pragma unroll
    for (int t = 0; t < 4; t++) {
        int idx = tid + t * 256;
        int tile = idx >> 9;
        int r = (idx >> 4) & 31;
        int c16 = idx & 15;
        const bf16* src = (tile ? WL : WH) + (size_t)(ck + r) * N + colBase + c16 * 8;
        uint32_t dst = st + (tile ? BL_OFF : BH_OFF) + r * B_STRIDE + c16 * 16;
        CP_ASYNC(dst, src);
    }
}

template<int MODE>
__global__ void __launch_bounds__(256, 2) hmma2(
    const bf16* __restrict__ AH, const bf16* __restrict__ AL,
    const bf16* __restrict__ WH, const bf16* __restrict__ WL,
    const float* __restrict__ bias, float* __restrict__ C,
    bf16* __restrict__ CH, bf16* __restrict__ CL,
    int M, int N, int K, long long Wz, long long bz, long long Cz)
{
    extern __shared__ char smem[];
    const int z = blockIdx.z;
    WH += (size_t)z * Wz; WL += (size_t)z * Wz; bias += (size_t)z * bz;
    float* Cp = C + (size_t)z * Cz;

    const int tid  = threadIdx.x;
    const int lane = tid & 31;
    const int wid  = tid >> 5;
    const int m0   = (wid & 3) << 5;
    const int n0w  = (wid >> 2) << 6;
    const int rowBase = blockIdx.y << 7;
    const int colBase = blockIdx.x << 7;
    const int NC = K >> 5;

    uint32_t sbase = smem_u32(smem);

    float acc[2][8][4];
#pragma unroll
    for (int a = 0; a < 2; a++)
#pragma unroll
        for (int b = 0; b < 8; b++)
#pragma unroll
            for (int c = 0; c < 4; c++) acc[a][b][c] = 0.f;

    load_stage(AH, AL, WH, WL, K, N, rowBase, colBase, 0, sbase, tid);
    CP_COMMIT();
    load_stage(AH, AL, WH, WL, K, N, rowBase, colBase, 32, sbase + STAGE_B, tid);
    CP_COMMIT();
    CP_WAIT(1);
    __syncthreads();

    const int arow = lane & 15;
    const int aoff = (lane >> 4) << 4;

    for (int c = 0; c < NC; c++) {
        uint32_t cur = sbase + (c & 1) * STAGE_B;
#pragma unroll
        for (int ks = 0; ks < 32; ks += 16) {
            uint32_t ah[2][4], al[2][4];
#pragma unroll
            for (int mt = 0; mt < 2; mt++) {
                uint32_t ad = cur + (uint32_t)((m0 + mt * 16 + arow) * A_STRIDE + ks * 2 + aoff);
                ldsm4(ah[mt], ad);
                ldsm4(al[mt], ad + AL_OFF);
            }
#pragma unroll
            for (int np = 0; np < 4; np++) {
                uint32_t bh[4], bl[4];
                uint32_t bd = cur + BH_OFF +
                    (uint32_t)((ks + arow) * B_STRIDE + ((n0w + np * 16) << 1) + aoff);
                ldsm4t(bh, bd);
                ldsm4t(bl, bd + (BL_OFF - BH_OFF));
#pragma unroll
                for (int mt = 0; mt < 2; mt++)
#pragma unroll
                    for (int e = 0; e < 2; e++) {
                        uint32_t bfh[2] = { bh[2 * e], bh[2 * e + 1] };
                        uint32_t bfl[2] = { bl[2 * e], bl[2 * e + 1] };
                        float* d = acc[mt][np * 2 + e];
                        mma16816(d, ah[mt], bfh);
                        mma16816(d, al[mt], bfh);
                        mma16816(d, ah[mt], bfl);
                    }
            }
        }
        __syncthreads();
        if (c + 2 < NC) {
            load_stage(AH, AL, WH, WL, K, N, rowBase, colBase, (c + 2) << 5,
                       sbase + (c & 1) * STAGE_B, tid);
            CP_COMMIT();
            CP_WAIT(1);
        } else {
            CP_WAIT(0);
        }
        __syncthreads();
    }

    // ---- epilogue ----
#pragma unroll
    for (int mt = 0; mt < 2; mt++) {
        const int r0 = rowBase + m0 + mt * 16 + (lane >> 2);
#pragma unroll
        for (int nt = 0; nt < 8; nt++) {
            const int c0 = colBase + n0w + nt * 8 + ((lane & 3) << 1);
            float* d = acc[mt][nt];
            float b0 = bias[c0], b1 = bias[c0 + 1];
#pragma unroll
            for (int half = 0; half < 2; half++) {
                const int row = r0 + half * 8;
                float v0 = d[half * 2 + 0] + b0;
                float v1 = d[half * 2 + 1] + b1;
                if (MODE == 0) {
                    float* out = Cp + (size_t)row * N + c0;
                    out[0] = v0; out[1] = v1;
                } else if (MODE == 1) {
                    float* out = Cp + (size_t)row * N + c0;
                    out[0] += v0; out[1] += v1;
                } else {
                    float g0 = 0.5f * v0 * (1.f + erff(v0 * 0.70710678118654752f));
                    float g1 = 0.5f * v1 * (1.f + erff(v1 * 0.70710678118654752f));
                    uint32_t hi, lo;
                    split2(g0, g1, hi, lo);
                    *(uint32_t*)(CH + (size_t)row * N + c0) = hi;
                    *(uint32_t*)(CL + (size_t)row * N + c0) = lo;
                }
            }
        }
    }
}

// ---------------- mask dtype detection ----------------
__global__ void detect_mask_kernel(const void* m) {
    __shared__ int flags[2];
    if (threadIdx.x == 0) { flags[0] = 0; flags[1] = 0; }
    __syncthreads();
    unsigned v = ((const unsigned*)m)[threadIdx.x];
    if (v > 1u) flags[0] = 1;
    if (v != 0u && v != 0x3F800000u) flags[1] = 1;
    __syncthreads();
    if (threadIdx.x == 0)
        g_mask_mode = (!flags[0]) ? 1 : ((!flags[1]) ? 2 : 0);
}

// ---------------- LayerNorm -> split bf16 output ----------------
__global__ __launch_bounds__(256) void ln_kernel(
    const float* __restrict__ x, const float* __restrict__ g,
    const float* __restrict__ b, bf16* __restrict__ outH, bf16* __restrict__ outL)
{
    int row = blockIdx.x;
    int tid = threadIdx.x;
    const float* xr = x + (size_t)row * D_;
    float4 v = *(const float4*)(xr + tid * 4);
    float s  = v.x + v.y + v.z + v.w;
    float s2 = v.x * v.x + v.y * v.y + v.z * v.z + v.w * v.w;
    __shared__ float r1[256], r2[256];
    r1[tid] = s; r2[tid] = s2;
    __syncthreads();
    for (int off = 128; off > 0; off >>= 1) {
        if (tid < off) { r1[tid] += r1[tid + off]; r2[tid] += r2[tid + off]; }
        __syncthreads();
    }
    float mean = r1[0] * (1.f / D_);
    float var  = r2[0] * (1.f / D_) - mean * mean;
    float rstd = rsqrtf(var + 1e-5f);
    float4 gv = *(const float4*)(g + tid * 4);
    float4 bv = *(const float4*)(b + tid * 4);
    float o0 = (v.x - mean) * rstd * gv.x + bv.x;
    float o1 = (v.y - mean) * rstd * gv.y + bv.y;
    float o2 = (v.z - mean) * rstd * gv.z + bv.z;
    float o3 = (v.w - mean) * rstd * gv.w + bv.w;
    uint32_t h01, l01, h23, l23;
    split2(o0, o1, h01, l01);
    split2(o2, o3, h23, l23);
    size_t base = (size_t)row * D_ + tid * 4;
    *(uint2*)(outH + base) = make_uint2(h01, h23);
    *(uint2*)(outL + base) = make_uint2(l01, l23);
}

// ---------------- RoPE in place ----------------
__global__ void rope_kernel(float* __restrict__ q) {
    int idx = blockIdx.x * blockDim.x + threadIdx.x;
    int i = idx & 31;
    int h = (idx >> 5) & (H_ - 1);
    int r = idx >> 9;
    int s = r >> 2;
    float inv = expf(-0.28782313662425572f * (float)i);
    float ang = (float)s * inv;
    float c, sn;
    sincosf(ang, &sn, &c);
    float* base = q + (size_t)r * D_ + h * HD_ + i;
    float x1 = base[0], x2 = base[32];
    base[0]  = x1 * c - x2 * sn;
    base[32] = x2 * c + x1 * sn;
}

// ---------------- x += dur[r]*Wdur[c] + bdur[c] ----------------
__global__ void adddur_kernel(float* __restrict__ x, const float* __restrict__ dur,
                              const float* __restrict__ wd, const float* __restrict__ bd) {
    int idx = blockIdx.x * blockDim.x + threadIdx.x;
    int r = idx >> 10, c = idx & 1023;
    x[idx] += dur[r] * wd[c] + bd[c];
}

// ---------------- scores = q @ k^T (per b,h) ----------------
__global__ __launch_bounds__(256) void scores_kernel(
    const float* __restrict__ q, const float* __restrict__ k,
    float* __restrict__ scores)
{
    int bh = blockIdx.z;
    int b = bh >> 4, h = bh & 15;
    int q0 = blockIdx.y << 6, k0 = blockIdx.x << 6;
    __shared__ float Qs[64][65], Ks[64][65];
    int tid = threadIdx.x;
    const float* qb = q + (size_t)b * D_ + h * HD_;
    const float* kb = k + (size_t)b * D_ + h * HD_;
#pragma unroll
    for (int it = 0; it < 4; it++) {
        int e = tid + it * 256;
        int r = e >> 4, c = (e & 15) << 2;
        float4 v = *(const float4*)(qb + (size_t)(q0 + r) * (B_ * D_) + c);
        Qs[r][c] = v.x; Qs[r][c + 1] = v.y; Qs[r][c + 2] = v.z; Qs[r][c + 3] = v.w;
        float4 w = *(const float4*)(kb + (size_t)(k0 + r) * (B_ * D_) + c);
        Ks[r][c] = w.x; Ks[r][c + 1] = w.y; Ks[r][c + 2] = w.z; Ks[r][c + 3] = w.w;
    }
    __syncthreads();
    int tx = tid & 15, ty = tid >> 4;
    float acc[4][4] = {};
#pragma unroll 16
    for (int d = 0; d < 64; d++) {
        float a[4], bb[4];
#pragma unroll
        for (int i = 0; i < 4; i++) a[i]  = Qs[ty * 4 + i][d];
#pragma unroll
        for (int j = 0; j < 4; j++) bb[j] = Ks[tx * 4 + j][d];
#pragma unroll
        for (int i = 0; i < 4; i++)
#pragma unroll
            for (int j = 0; j < 4; j++)
                acc[i][j] = fmaf(a[i], bb[j], acc[i][j]);
    }
    float* out = scores + ((size_t)bh * S_ + q0) * S_ + k0;
#pragma unroll
    for (int i = 0; i < 4; i++)
#pragma unroll
        for (int j = 0; j < 4; j++)
            out[(size_t)(ty * 4 + i) * S_ + tx * 4 + j] = acc[i][j];
}

// ---------------- masked softmax ----------------
__global__ __launch_bounds__(128) void softmax_kernel(
    float* __restrict__ scores, const void* __restrict__ maskp)
{
    int row = blockIdx.x;
    int bh  = row >> 9;
    int b   = bh >> 4;
    float* p = scores + (size_t)row * S_;
    int mode = g_mask_mode;
    const unsigned char* mu8 = (const unsigned char*)maskp;
    const int*   mi = (const int*)maskp;
    const float* mf = (const float*)maskp;
    int tid = threadIdx.x;
    float v[4];
    float mx = -1e30f;
#pragma unroll
    for (int kq = 0; kq < 4; kq++) {
        int j = tid + kq * 128;
        float s = p[j] * 0.125f;
        bool m;
        if (mode == 1)      m = mi[b * S_ + j] != 0;
        else if (mode == 2) m = mf[b * S_ + j] != 0.f;
        else                m = mu8[b * S_ + j] != 0;
        v[kq] = m ? -1e30f : s;
        mx = fmaxf(mx, v[kq]);
    }
    __shared__ float red[128];
    red[tid] = mx; __syncthreads();
    for (int off = 64; off > 0; off >>= 1) {
        if (tid < off) red[tid] = fmaxf(red[tid], red[tid + off]);
        __syncthreads();
    }
    mx = red[0]; __syncthreads();
    float sum = 0.f;
#pragma unroll
    for (int kq = 0; kq < 4; kq++) { v[kq] = expf(v[kq] - mx); sum += v[kq]; }
    red[tid] = sum; __syncthreads();
    for (int off = 64; off > 0; off >>= 1) {
        if (tid < off) red[tid] += red[tid + off];
        __syncthreads();
    }
    float inv = 1.f / red[0];
#pragma unroll
    for (int kq = 0; kq < 4; kq++) p[tid + kq * 128] = v[kq] * inv;
}

// ---------------- attn = probs @ V -> split bf16 [S,B,D] ----------------
__global__ __launch_bounds__(256) void attnv_kernel(
    const float* __restrict__ probs, const float* __restrict__ v,
    bf16* __restrict__ attnH, bf16* __restrict__ attnL)
{
    int bh = blockIdx.y;
    int b = bh >> 4, h = bh & 15;
    int q0 = blockIdx.x << 6;
    __shared__ float Ps[64][33];
    __shared__ float Vs[32][64];
    int tid = threadIdx.x;
    int tx = tid & 15, ty = tid >> 4;
    float acc[4][4] = {};
    const float* pb = probs + ((size_t)bh * S_ + q0) * S_;
    const float* vb = v + (size_t)b * D_ + h * HD_;
    for (int kt = 0; kt < S_; kt += 32) {
#pragma unroll
        for (int it = 0; it < 2; it++) {
            int e = tid + it * 256;
            int r = e >> 3, c = (e & 7) << 2;
            float4 pv = *(const float4*)(pb + (size_t)r * S_ + kt + c);
            Ps[r][c] = pv.x; Ps[r][c + 1] = pv.y; Ps[r][c + 2] = pv.z; Ps[r][c + 3] = pv.w;
            int r2 = e >> 4, c2 = (e & 15) << 2;
            *(float4*)(&Vs[r2][c2]) = *(const float4*)(vb + (size_t)(kt + r2) * (B_ * D_) + c2);
        }
        __syncthreads();
#pragma unroll
        for (int kk = 0; kk < 32; kk++) {
            float a[4];
#pragma unroll
            for (int i = 0; i < 4; i++) a[i] = Ps[ty * 4 + i][kk];
            float4 bv4 = *(const float4*)(&Vs[kk][tx * 4]);
            float bb[4] = { bv4.x, bv4.y, bv4.z, bv4.w };
#pragma unroll
            for (int i = 0; i < 4; i++)
#pragma unroll
                for (int j = 0; j < 4; j++)
                    acc[i][j] = fmaf(a[i], bb[j], acc[i][j]);
        }
        __syncthreads();
    }
#pragma unroll
    for (int i = 0; i < 4; i++) {
        int qi = q0 + ty * 4 + i;
        size_t base = ((size_t)qi * B_ + b) * D_ + h * HD_ + tx * 4;
        uint32_t h01, l01, h23, l23;
        split2(acc[i][0], acc[i][1], h01, l01);
        split2(acc[i][2], acc[i][3], h23, l23);
        *(uint2*)(attnH + base) = make_uint2(h01, h23);
        *(uint2*)(attnL + base) = make_uint2(l01, l23);
    }
}

// ---------------- host orchestration ----------------
extern "C" void kernel_launch(void* const* d_in, const int* in_sizes, int n_in,
                              void* d_out, int out_size)
{
    (void)in_sizes; (void)n_in; (void)out_size;
    const float* segments  = (const float*)d_in[0];
    const float* durations = (const float*)d_in[1];
    const void*  mask      = d_in[2];
    const float* Wproj = (const float*)d_in[3];
    const float* bproj = (const float*)d_in[4];
    const float* Wdur  = (const float*)d_in[5];
    const float* bdur  = (const float*)d_in[6];
    const float* ln1g  = (const float*)d_in[7];
    const float* ln1b  = (const float*)d_in[8];
    const float* Wq    = (const float*)d_in[9];
    const float* bq    = (const float*)d_in[10];
    const float* Wk    = (const float*)d_in[11];
    const float* bk    = (const float*)d_in[12];
    const float* Wv    = (const float*)d_in[13];
    const float* bv    = (const float*)d_in[14];
    const float* Wo    = (const float*)d_in[15];
    const float* bo    = (const float*)d_in[16];
    const float* ln2g  = (const float*)d_in[17];
    const float* ln2b  = (const float*)d_in[18];
    const float* W1    = (const float*)d_in[19];
    const float* b1    = (const float*)d_in[20];
    const float* W2    = (const float*)d_in[21];
    const float* b2    = (const float*)d_in[22];
    float* x = (float*)d_out;

    bf16 *wqkvH, *wqkvL, *woH, *woL, *w1H, *w1L, *w2H, *w2L, *wpH, *wpL;
    bf16 *segH, *segL, *hH, *hL, *aH, *aL, *ffH, *ffL;
    float *bqkv, *qkv, *scores;
    cudaGetSymbolAddress((void**)&wqkvH, g_wqkv_h);
    cudaGetSymbolAddress((void**)&wqkvL, g_wqkv_l);
    cudaGetSymbolAddress((void**)&woH,   g_wo_h);
    cudaGetSymbolAddress((void**)&woL,   g_wo_l);
    cudaGetSymbolAddress((void**)&w1H,   g_w1_h);
    cudaGetSymbolAddress((void**)&w1L,   g_w1_l);
    cudaGetSymbolAddress((void**)&w2H,   g_w2_h);
    cudaGetSymbolAddress((void**)&w2L,   g_w2_l);
    cudaGetSymbolAddress((void**)&wpH,   g_wp_h);
    cudaGetSymbolAddress((void**)&wpL,   g_wp_l);
    cudaGetSymbolAddress((void**)&segH,  g_seg_h);
    cudaGetSymbolAddress((void**)&segL,  g_seg_l);
    cudaGetSymbolAddress((void**)&hH,    g_hh);
    cudaGetSymbolAddress((void**)&hL,    g_hl);
    cudaGetSymbolAddress((void**)&aH,    g_ah);
    cudaGetSymbolAddress((void**)&aL,    g_al);
    cudaGetSymbolAddress((void**)&ffH,   g_ffh);
    cudaGetSymbolAddress((void**)&ffL,   g_ffl);
    cudaGetSymbolAddress((void**)&bqkv,  g_bqkv);
    cudaGetSymbolAddress((void**)&qkv,   g_qkv);
    cudaGetSymbolAddress((void**)&scores, g_scores);

    cudaFuncSetAttribute(hmma2<0>, cudaFuncAttributeMaxDynamicSharedMemorySize, GEMM_SMEM);
    cudaFuncSetAttribute(hmma2<1>, cudaFuncAttributeMaxDynamicSharedMemorySize, GEMM_SMEM);
    cudaFuncSetAttribute(hmma2<2>, cudaFuncAttributeMaxDynamicSharedMemorySize, GEMM_SMEM);

    detect_mask_kernel<<<1, 512>>>(mask);

    // ---- one-time (per launch) weight splitting ----
    const int CT = 256;
    int nqkv = L_ * DD_;
    conv_split<<<(nqkv + CT - 1) / CT, CT>>>(Wq, wqkvH, wqkvL, nqkv, DD_, 3, 0);
    conv_split<<<(nqkv + CT - 1) / CT, CT>>>(Wk, wqkvH, wqkvL, nqkv, DD_, 3, 1);
    conv_split<<<(nqkv + CT - 1) / CT, CT>>>(Wv, wqkvH, wqkvL, nqkv, DD_, 3, 2);
    conv_split<<<(nqkv + CT - 1) / CT, CT>>>(Wo, woH, woL, nqkv, 1, 1, 0);
    int nff = L_ * DF_;
    conv_split<<<(nff + CT - 1) / CT, CT>>>(W1, w1H, w1L, nff, 1, 1, 0);
    conv_split<<<(nff + CT - 1) / CT, CT>>>(W2, w2H, w2L, nff, 1, 1, 0);
    conv_split<<<(DIN_ * D_ + CT - 1) / CT, CT>>>(Wproj, wpH, wpL, DIN_ * D_, 1, 1, 0);
    conv_split<<<(SB_ * DIN_ + CT - 1) / CT, CT>>>(segments, segH, segL, SB_ * DIN_, 1, 1, 0);
    int nb = L_ * D_;
    map_bias<<<(nb + CT - 1) / CT, CT>>>(bq, bqkv, nb, D_, 3, 0);
    map_bias<<<(nb + CT - 1) / CT, CT>>>(bk, bqkv, nb, D_, 3, 1);
    map_bias<<<(nb + CT - 1) / CT, CT>>>(bv, bqkv, nb, D_, 3, 2);

    dim3 gD(D_ / 128, SB_ / 128);           // (8,16)
    dim3 gQKV(D_ / 128, SB_ / 128, 3);      // (8,16,3)
    dim3 gF(F_ / 128, SB_ / 128);           // (32,16)

    // input projection
    hmma2<0><<<gD, 256, GEMM_SMEM>>>(segH, segL, wpH, wpL, bproj, x, nullptr, nullptr,
                                     SB_, D_, DIN_, 0, 0, 0);
    adddur_kernel<<<(SB_ * D_) / 256, 256>>>(x, durations, Wdur, bdur);

    float* q  = qkv;
    float* k  = qkv + (size_t)SB_ * D_;
    float* v  = qkv + 2 * (size_t)SB_ * D_;

    for (int l = 0; l < L_; l++) {
        ln_kernel<<<SB_, 256>>>(x, ln1g + (size_t)l * D_, ln1b + (size_t)l * D_, hH, hL);
        hmma2<0><<<gQKV, 256, GEMM_SMEM>>>(hH, hL,
            wqkvH + (size_t)l * 3 * DD_, wqkvL + (size_t)l * 3 * DD_,
            bqkv + (size_t)l * 3 * D_, qkv, nullptr, nullptr,
            SB_, D_, D_, DD_, D_, (long long)SB_ * D_);
        rope_kernel<<<(SB_ * H_ * 32) / 256, 256>>>(q);
        rope_kernel<<<(SB_ * H_ * 32) / 256, 256>>>(k);
        scores_kernel<<<dim3(8, 8, BH_), 256>>>(q, k, scores);
        softmax_kernel<<<BH_ * S_, 128>>>(scores, mask);
        attnv_kernel<<<dim3(8, BH_), 256>>>(scores, v, aH, aL);
        hmma2<1><<<gD, 256, GEMM_SMEM>>>(aH, aL,
            woH + (size_t)l * DD_, woL + (size_t)l * DD_,
            bo + (size_t)l * D_, x, nullptr, nullptr, SB_, D_, D_, 0, 0, 0);
        ln_kernel<<<SB_, 256>>>(x, ln2g + (size_t)l * D_, ln2b + (size_t)l * D_, hH, hL);
        hmma2<2><<<gF, 256, GEMM_SMEM>>>(hH, hL,
            w1H + (size_t)l * DF_, w1L + (size_t)l * DF_,
            b1 + (size_t)l * F_, nullptr, ffH, ffL, SB_, F_, D_, 0, 0, 0);
        hmma2<1><<<gD, 256, GEMM_SMEM>>>(ffH, ffL,
            w2H + (size_t)l * DF_, w2L + (size_t)l * DF_,
            b2 + (size_t)l * D_, x, nullptr, nullptr, SB_, D_, F_, 0, 0, 0);
    }
}

// round 8
// speedup vs baseline: 2.7196x; 1.1398x over previous
#include <cuda_runtime.h>
#include <cuda_bf16.h>
#include <math.h>
#include <stdint.h>

#define L_   12
#define S_   512
#define B_   4
#define DIN_ 768
#define D_   1024
#define H_   16
#define F_   4096
#define HD_  64
#define SB_  2048
#define BH_  (B_*H_)
#define DD_  (D_*D_)
#define DF_  (D_*F_)

typedef __nv_bfloat16 bf16;

// ---------------- persistent scratch (device globals) ----------------
__device__ __align__(16) bf16 g_wqkv_h[(size_t)L_*3*DD_];
__device__ __align__(16) bf16 g_wqkv_l[(size_t)L_*3*DD_];
__device__ __align__(16) bf16 g_wo_h  [(size_t)L_*DD_];
__device__ __align__(16) bf16 g_wo_l  [(size_t)L_*DD_];
__device__ __align__(16) bf16 g_w1_h  [(size_t)L_*DF_];
__device__ __align__(16) bf16 g_w1_l  [(size_t)L_*DF_];
__device__ __align__(16) bf16 g_w2_h  [(size_t)L_*DF_];
__device__ __align__(16) bf16 g_w2_l  [(size_t)L_*DF_];
__device__ __align__(16) bf16 g_wp_h  [DIN_*D_];
__device__ __align__(16) bf16 g_wp_l  [DIN_*D_];
__device__ float g_bqkv[L_*3*D_];
__device__ __align__(16) bf16 g_seg_h[SB_*DIN_];
__device__ __align__(16) bf16 g_seg_l[SB_*DIN_];
__device__ __align__(16) bf16 g_hh[SB_*D_];
__device__ __align__(16) bf16 g_hl[SB_*D_];
__device__ __align__(16) bf16 g_ah[SB_*D_];
__device__ __align__(16) bf16 g_al[SB_*D_];
__device__ __align__(16) bf16 g_ffh[(size_t)SB_*F_];
__device__ __align__(16) bf16 g_ffl[(size_t)SB_*F_];
__device__ float g_qkv[3*SB_*D_];
__device__ float g_scores[(size_t)BH_*S_*S_];
__device__ __align__(16) bf16 g_qh[SB_*D_];
__device__ __align__(16) bf16 g_ql[SB_*D_];
__device__ __align__(16) bf16 g_kh[SB_*D_];
__device__ __align__(16) bf16 g_kl[SB_*D_];
__device__ __align__(16) bf16 g_vh[SB_*D_];
__device__ __align__(16) bf16 g_vl[SB_*D_];
__device__ __align__(16) bf16 g_ph[(size_t)BH_*S_*S_];
__device__ __align__(16) bf16 g_pl[(size_t)BH_*S_*S_];
__device__ int   g_mask_mode;

// ============================================================================
// helpers
// ============================================================================
__device__ __forceinline__ uint32_t smem_u32(const void* p) {
    uint32_t a;
    asm("{ .reg .u64 t; cvta.to.shared.u64 t, %1; cvt.u32.u64 %0, t; }"
        : "=r"(a) : "l"(p));
    return a;
}
__device__ __forceinline__ void ldsm4(uint32_t* r, uint32_t addr) {
    asm volatile("ldmatrix.sync.aligned.m8n8.x4.shared.b16 {%0,%1,%2,%3}, [%4];"
                 : "=r"(r[0]), "=r"(r[1]), "=r"(r[2]), "=r"(r[3]) : "r"(addr));
}
__device__ __forceinline__ void ldsm4t(uint32_t* r, uint32_t addr) {
    asm volatile("ldmatrix.sync.aligned.m8n8.x4.trans.shared.b16 {%0,%1,%2,%3}, [%4];"
                 : "=r"(r[0]), "=r"(r[1]), "=r"(r[2]), "=r"(r[3]) : "r"(addr));
}
__device__ __forceinline__ void mma16816(float* d, const uint32_t* a, const uint32_t* b) {
    asm volatile(
        "mma.sync.aligned.m16n8k16.row.col.f32.bf16.bf16.f32 "
        "{%0,%1,%2,%3}, {%4,%5,%6,%7}, {%8,%9}, {%0,%1,%2,%3};"
        : "+f"(d[0]), "+f"(d[1]), "+f"(d[2]), "+f"(d[3])
        : "r"(a[0]), "r"(a[1]), "r"(a[2]), "r"(a[3]), "r"(b[0]), "r"(b[1]));
}
#define CP_ASYNC(dst, src) \
    asm volatile("cp.async.cg.shared.global [%0], [%1], 16;" :: "r"(dst), "l"(src))
#define CP_COMMIT() asm volatile("cp.async.commit_group;")
#define CP_WAIT(n)  asm volatile("cp.async.wait_group %0;" :: "n"(n))

__device__ __forceinline__ void split2(float v0, float v1, uint32_t& hi, uint32_t& lo) {
    __nv_bfloat162 h = __floats2bfloat162_rn(v0, v1);
    __nv_bfloat162 l = __floats2bfloat162_rn(v0 - __bfloat162float(h.x),
                                             v1 - __bfloat162float(h.y));
    hi = *(uint32_t*)&h; lo = *(uint32_t*)&l;
}

// ============================================================================
// conversions
// ============================================================================
__global__ void conv_split(const float* __restrict__ src, bf16* __restrict__ dh,
                           bf16* __restrict__ dl, int n, int inner, int gm, int go) {
    int i = blockIdx.x * blockDim.x + threadIdx.x;
    if (i >= n) return;
    float v = src[i];
    bf16 h = __float2bfloat16(v);
    float r = v - __bfloat162float(h);
    size_t d = (size_t)(i / inner) * inner * gm + (size_t)go * inner + (i % inner);
    dh[d] = h; dl[d] = __float2bfloat16(r);
}
__global__ void map_bias(const float* __restrict__ src, float* __restrict__ dst,
                         int n, int inner, int gm, int go) {
    int i = blockIdx.x * blockDim.x + threadIdx.x;
    if (i >= n) return;
    dst[(size_t)(i / inner) * inner * gm + (size_t)go * inner + (i % inner)] = src[i];
}

// ============================================================================
// split-bf16 HMMA GEMM (unchanged from round 5)
// ============================================================================
#define A_STRIDE   80
#define B_STRIDE   272
#define AH_OFF     0
#define AL_OFF     10240
#define BH_OFF     20480
#define BL_OFF     29184
#define STAGE_B    37888
#define GEMM_SMEM  (2*STAGE_B)

__device__ __forceinline__ void load_stage(
    const bf16* __restrict__ AH, const bf16* __restrict__ AL,
    const bf16* __restrict__ WH, const bf16* __restrict__ WL,
    int K, int N, int rowBase, int colBase, int ck, uint32_t st, int tid)
{
#pragma unroll
    for (int t = 0; t < 4; t++) {
        int idx = tid + t * 256;
        int tile = idx >> 9;
        int r = (idx >> 2) & 127;
        int c16 = idx & 3;
        const bf16* src = (tile ? AL : AH) + (size_t)(rowBase + r) * K + ck + c16 * 8;
        uint32_t dst = st + (tile ? AL_OFF : AH_OFF) + r * A_STRIDE + c16 * 16;
        CP_ASYNC(dst, src);
    }
#pragma unroll
    for (int t = 0; t < 4; t++) {
        int idx = tid + t * 256;
        int tile = idx >> 9;
        int r = (idx >> 4) & 31;
        int c16 = idx & 15;
        const bf16* src = (tile ? WL : WH) + (size_t)(ck + r) * N + colBase + c16 * 8;
        uint32_t dst = st + (tile ? BL_OFF : BH_OFF) + r * B_STRIDE + c16 * 16;
        CP_ASYNC(dst, src);
    }
}

template<int MODE>
__global__ void __launch_bounds__(256, 2) hmma2(
    const bf16* __restrict__ AH, const bf16* __restrict__ AL,
    const bf16* __restrict__ WH, const bf16* __restrict__ WL,
    const float* __restrict__ bias, float* __restrict__ C,
    bf16* __restrict__ CH, bf16* __restrict__ CL,
    int M, int N, int K, long long Wz, long long bz, long long Cz)
{
    extern __shared__ char smem[];
    const int z = blockIdx.z;
    WH += (size_t)z * Wz; WL += (size_t)z * Wz; bias += (size_t)z * bz;
    float* Cp = C + (size_t)z * Cz;

    const int tid  = threadIdx.x;
    const int lane = tid & 31;
    const int wid  = tid >> 5;
    const int m0   = (wid & 3) << 5;
    const int n0w  = (wid >> 2) << 6;
    const int rowBase = blockIdx.y << 7;
    const int colBase = blockIdx.x << 7;
    const int NC = K >> 5;

    uint32_t sbase = smem_u32(smem);

    float acc[2][8][4];
#pragma unroll
    for (int a = 0; a < 2; a++)
#pragma unroll
        for (int b = 0; b < 8; b++)
#pragma unroll
            for (int c = 0; c < 4; c++) acc[a][b][c] = 0.f;

    load_stage(AH, AL, WH, WL, K, N, rowBase, colBase, 0, sbase, tid);
    CP_COMMIT();
    load_stage(AH, AL, WH, WL, K, N, rowBase, colBase, 32, sbase + STAGE_B, tid);
    CP_COMMIT();
    CP_WAIT(1);
    __syncthreads();

    const int arow = lane & 15;
    const int aoff = (lane >> 4) << 4;

    for (int c = 0; c < NC; c++) {
        uint32_t cur = sbase + (c & 1) * STAGE_B;
#pragma unroll
        for (int ks = 0; ks < 32; ks += 16) {
            uint32_t ah[2][4], al[2][4];
#pragma unroll
            for (int mt = 0; mt < 2; mt++) {
                uint32_t ad = cur + (uint32_t)((m0 + mt * 16 + arow) * A_STRIDE + ks * 2 + aoff);
                ldsm4(ah[mt], ad);
                ldsm4(al[mt], ad + AL_OFF);
            }
#pragma unroll
            for (int np = 0; np < 4; np++) {
                uint32_t bh[4], bl[4];
                uint32_t bd = cur + BH_OFF +
                    (uint32_t)((ks + arow) * B_STRIDE + ((n0w + np * 16) << 1) + aoff);
                ldsm4t(bh, bd);
                ldsm4t(bl, bd + (BL_OFF - BH_OFF));
#pragma unroll
                for (int mt = 0; mt < 2; mt++)
#pragma unroll
                    for (int e = 0; e < 2; e++) {
                        uint32_t bfh[2] = { bh[2 * e], bh[2 * e + 1] };
                        uint32_t bfl[2] = { bl[2 * e], bl[2 * e + 1] };
                        float* d = acc[mt][np * 2 + e];
                        mma16816(d, ah[mt], bfh);
                        mma16816(d, al[mt], bfh);
                        mma16816(d, ah[mt], bfl);
                    }
            }
        }
        __syncthreads();
        if (c + 2 < NC) {
            load_stage(AH, AL, WH, WL, K, N, rowBase, colBase, (c + 2) << 5,
                       sbase + (c & 1) * STAGE_B, tid);
            CP_COMMIT();
            CP_WAIT(1);
        } else {
            CP_WAIT(0);
        }
        __syncthreads();
    }

#pragma unroll
    for (int mt = 0; mt < 2; mt++) {
        const int r0 = rowBase + m0 + mt * 16 + (lane >> 2);
#pragma unroll
        for (int nt = 0; nt < 8; nt++) {
            const int c0 = colBase + n0w + nt * 8 + ((lane & 3) << 1);
            float* d = acc[mt][nt];
            float b0 = bias[c0], b1 = bias[c0 + 1];
#pragma unroll
            for (int half = 0; half < 2; half++) {
                const int row = r0 + half * 8;
                float v0 = d[half * 2 + 0] + b0;
                float v1 = d[half * 2 + 1] + b1;
                if (MODE == 0) {
                    float* out = Cp + (size_t)row * N + c0;
                    out[0] = v0; out[1] = v1;
                } else if (MODE == 1) {
                    float* out = Cp + (size_t)row * N + c0;
                    out[0] += v0; out[1] += v1;
                } else {
                    float g0 = 0.5f * v0 * (1.f + erff(v0 * 0.70710678118654752f));
                    float g1 = 0.5f * v1 * (1.f + erff(v1 * 0.70710678118654752f));
                    uint32_t hi, lo;
                    split2(g0, g1, hi, lo);
                    *(uint32_t*)(CH + (size_t)row * N + c0) = hi;
                    *(uint32_t*)(CL + (size_t)row * N + c0) = lo;
                }
            }
        }
    }
}

// ============================================================================
// HMMA attention: scores = Q @ K^T per (b,h)  [3-term split]
// ============================================================================
#define QS_STRIDE 144
#define SC_TILE   18432            // 128 * 144
#define SC_SMEM   (4*SC_TILE)      // Qh, Ql, Kh, Kl

__global__ void __launch_bounds__(256) scores_hmma(
    const bf16* __restrict__ qh, const bf16* __restrict__ ql,
    const bf16* __restrict__ kh, const bf16* __restrict__ kl,
    float* __restrict__ scores)
{
    extern __shared__ char smem[];
    const int bh = blockIdx.z;
    const int b = bh >> 4, h = bh & 15;
    const int q0 = blockIdx.y << 7, k0 = blockIdx.x << 7;
    const int tid = threadIdx.x;
    const int lane = tid & 31;
    const int wid  = tid >> 5;
    const int m0   = (wid & 3) << 5;
    const int n0w  = (wid >> 2) << 6;

    uint32_t sbase = smem_u32(smem);
    const size_t hoff = (size_t)b * D_ + h * HD_;

    // load 4 tiles: 4096 16B-chunks, 16 per thread
#pragma unroll
    for (int t = 0; t < 16; t++) {
        int idx = tid + t * 256;
        int tile = idx >> 10;                 // 0=qh 1=ql 2=kh 3=kl
        int r = (idx >> 3) & 127;
        int c = idx & 7;
        const bf16* base = (tile == 0) ? qh : (tile == 1) ? ql : (tile == 2) ? kh : kl;
        int rowg = (tile < 2 ? q0 : k0) + r;
        const bf16* src = base + (size_t)rowg * (B_ * D_) + hoff + c * 8;
        CP_ASYNC(sbase + tile * SC_TILE + r * QS_STRIDE + c * 16, src);
    }
    CP_COMMIT();
    CP_WAIT(0);
    __syncthreads();

    float acc[2][8][4];
#pragma unroll
    for (int a = 0; a < 2; a++)
#pragma unroll
        for (int bb = 0; bb < 8; bb++)
#pragma unroll
            for (int c = 0; c < 4; c++) acc[a][bb][c] = 0.f;

    const int arow = lane & 15;
    const int aoff = (lane >> 4) << 4;

#pragma unroll
    for (int ks = 0; ks < 64; ks += 16) {
        uint32_t ah[2][4], al[2][4];
#pragma unroll
        for (int mt = 0; mt < 2; mt++) {
            uint32_t ad = sbase + (uint32_t)((m0 + mt * 16 + arow) * QS_STRIDE + ks * 2 + aoff);
            ldsm4(ah[mt], ad);
            ldsm4(al[mt], ad + SC_TILE);
        }
#pragma unroll
        for (int np = 0; np < 4; np++) {
            uint32_t bhf[4], blf[4];
            uint32_t bd = sbase + 2 * SC_TILE +
                (uint32_t)((n0w + np * 16 + arow) * QS_STRIDE + ks * 2 + aoff);
            ldsm4(bhf, bd);
            ldsm4(blf, bd + SC_TILE);
#pragma unroll
            for (int mt = 0; mt < 2; mt++)
#pragma unroll
                for (int e = 0; e < 2; e++) {
                    // non-trans B: e=0 -> {r0,r2}, e=1 -> {r1,r3}
                    uint32_t bfh[2] = { bhf[e], bhf[e + 2] };
                    uint32_t bfl[2] = { blf[e], blf[e + 2] };
                    float* d = acc[mt][np * 2 + e];
                    mma16816(d, ah[mt], bfh);
                    mma16816(d, al[mt], bfh);
                    mma16816(d, ah[mt], bfl);
                }
        }
    }

#pragma unroll
    for (int mt = 0; mt < 2; mt++) {
        const int r0 = q0 + m0 + mt * 16 + (lane >> 2);
#pragma unroll
        for (int nt = 0; nt < 8; nt++) {
            const int c0 = k0 + n0w + nt * 8 + ((lane & 3) << 1);
            float* d = acc[mt][nt];
#pragma unroll
            for (int half = 0; half < 2; half++) {
                float* out = scores + ((size_t)bh * S_ + r0 + half * 8) * S_ + c0;
                out[0] = d[half * 2 + 0];
                out[1] = d[half * 2 + 1];
            }
        }
    }
}

// ============================================================================
// HMMA attn = P @ V per (b,h): A = ph/pl [S,S], W = vh/vl [S,B,D] slice
// CTA tile 128 x 64, K chunks of 32, 2-stage pipeline. Output split bf16.
// ============================================================================
#define AV_PH    0
#define AV_PL    10240
#define AV_VH    20480
#define AV_VL    25088
#define AV_STAGE 29696
#define AV_SMEM  (2*AV_STAGE)

__device__ __forceinline__ void av_load(
    const bf16* __restrict__ ph, const bf16* __restrict__ pl,
    const bf16* __restrict__ vh, const bf16* __restrict__ vl,
    int bh, int b, size_t hoff, int q0, int ck, uint32_t st, int tid)
{
#pragma unroll
    for (int t = 0; t < 4; t++) {
        int idx = tid + t * 256;
        int tile = idx >> 9;
        int r = (idx >> 2) & 127;
        int c = idx & 3;
        const bf16* src = (tile ? pl : ph) + ((size_t)bh * S_ + q0 + r) * S_ + ck + c * 8;
        CP_ASYNC(st + (tile ? AV_PL : AV_PH) + r * A_STRIDE + c * 16, src);
    }
#pragma unroll
    for (int t = 0; t < 2; t++) {
        int idx = tid + t * 256;
        int tile = idx >> 8;
        int r = (idx >> 3) & 31;
        int c = idx & 7;
        const bf16* src = (tile ? vl : vh) + (size_t)(ck + r) * (B_ * D_) + hoff + c * 8;
        CP_ASYNC(st + (tile ? AV_VL : AV_VH) + r * QS_STRIDE + c * 16, src);
    }
}

__global__ void __launch_bounds__(256) attnv_hmma(
    const bf16* __restrict__ ph, const bf16* __restrict__ pl,
    const bf16* __restrict__ vh, const bf16* __restrict__ vl,
    bf16* __restrict__ aH, bf16* __restrict__ aL)
{
    extern __shared__ char smem[];
    const int bh = blockIdx.y;
    const int b = bh >> 4, h = bh & 15;
    const int q0 = blockIdx.x << 7;
    const int tid = threadIdx.x;
    const int lane = tid & 31;
    const int wid  = tid >> 5;
    const int m0   = (wid & 3) << 5;
    const int n0w  = (wid >> 2) << 5;
    const size_t hoff = (size_t)b * D_ + h * HD_;

    uint32_t sbase = smem_u32(smem);

    float acc[2][4][4];
#pragma unroll
    for (int a = 0; a < 2; a++)
#pragma unroll
        for (int bb = 0; bb < 4; bb++)
#pragma unroll
            for (int c = 0; c < 4; c++) acc[a][bb][c] = 0.f;

    av_load(ph, pl, vh, vl, bh, b, hoff, q0, 0, sbase, tid);
    CP_COMMIT();
    av_load(ph, pl, vh, vl, bh, b, hoff, q0, 32, sbase + AV_STAGE, tid);
    CP_COMMIT();
    CP_WAIT(1);
    __syncthreads();

    const int arow = lane & 15;
    const int aoff = (lane >> 4) << 4;

    for (int c = 0; c < 16; c++) {
        uint32_t cur = sbase + (c & 1) * AV_STAGE;
#pragma unroll
        for (int ks = 0; ks < 32; ks += 16) {
            uint32_t ahf[2][4], alf[2][4];
#pragma unroll
            for (int mt = 0; mt < 2; mt++) {
                uint32_t ad = cur + (uint32_t)((m0 + mt * 16 + arow) * A_STRIDE + ks * 2 + aoff);
                ldsm4(ahf[mt], ad);
                ldsm4(alf[mt], ad + AV_PL);
            }
#pragma unroll
            for (int np = 0; np < 2; np++) {
                uint32_t bhf[4], blf[4];
                uint32_t bd = cur + AV_VH +
                    (uint32_t)((ks + arow) * QS_STRIDE + ((n0w + np * 16) << 1) + aoff);
                ldsm4t(bhf, bd);
                ldsm4t(blf, bd + (AV_VL - AV_VH));
#pragma unroll
                for (int mt = 0; mt < 2; mt++)
#pragma unroll
                    for (int e = 0; e < 2; e++) {
                        uint32_t bfh[2] = { bhf[2 * e], bhf[2 * e + 1] };
                        uint32_t bfl[2] = { blf[2 * e], blf[2 * e + 1] };
                        float* d = acc[mt][np * 2 + e];
                        mma16816(d, ahf[mt], bfh);
                        mma16816(d, alf[mt], bfh);
                        mma16816(d, ahf[mt], bfl);
                    }
            }
        }
        __syncthreads();
        if (c + 2 < 16) {
            av_load(ph, pl, vh, vl, bh, b, hoff, q0, (c + 2) << 5,
                    sbase + (c & 1) * AV_STAGE, tid);
            CP_COMMIT();
            CP_WAIT(1);
        } else {
            CP_WAIT(0);
        }
        __syncthreads();
    }

#pragma unroll
    for (int mt = 0; mt < 2; mt++) {
        const int r0 = q0 + m0 + mt * 16 + (lane >> 2);
#pragma unroll
        for (int nt = 0; nt < 4; nt++) {
            const int c0 = n0w + nt * 8 + ((lane & 3) << 1);
            float* d = acc[mt][nt];
#pragma unroll
            for (int half = 0; half < 2; half++) {
                size_t base = ((size_t)(r0 + half * 8)) * (B_ * D_) + hoff + c0;
                uint32_t hi, lo;
                split2(d[half * 2 + 0], d[half * 2 + 1], hi, lo);
                *(uint32_t*)(aH + base) = hi;
                *(uint32_t*)(aL + base) = lo;
            }
        }
    }
}

// ---------------- mask dtype detection ----------------
__global__ void detect_mask_kernel(const void* m) {
    __shared__ int flags[2];
    if (threadIdx.x == 0) { flags[0] = 0; flags[1] = 0; }
    __syncthreads();
    unsigned v = ((const unsigned*)m)[threadIdx.x];
    if (v > 1u) flags[0] = 1;
    if (v != 0u && v != 0x3F800000u) flags[1] = 1;
    __syncthreads();
    if (threadIdx.x == 0)
        g_mask_mode = (!flags[0]) ? 1 : ((!flags[1]) ? 2 : 0);
}

// ---------------- LayerNorm -> split bf16 ----------------
__global__ __launch_bounds__(256) void ln_kernel(
    const float* __restrict__ x, const float* __restrict__ g,
    const float* __restrict__ b, bf16* __restrict__ outH, bf16* __restrict__ outL)
{
    int row = blockIdx.x;
    int tid = threadIdx.x;
    const float* xr = x + (size_t)row * D_;
    float4 v = *(const float4*)(xr + tid * 4);
    float s  = v.x + v.y + v.z + v.w;
    float s2 = v.x * v.x + v.y * v.y + v.z * v.z + v.w * v.w;
    __shared__ float r1[256], r2[256];
    r1[tid] = s; r2[tid] = s2;
    __syncthreads();
    for (int off = 128; off > 0; off >>= 1) {
        if (tid < off) { r1[tid] += r1[tid + off]; r2[tid] += r2[tid + off]; }
        __syncthreads();
    }
    float mean = r1[0] * (1.f / D_);
    float var  = r2[0] * (1.f / D_) - mean * mean;
    float rstd = rsqrtf(var + 1e-5f);
    float4 gv = *(const float4*)(g + tid * 4);
    float4 bv = *(const float4*)(b + tid * 4);
    float o0 = (v.x - mean) * rstd * gv.x + bv.x;
    float o1 = (v.y - mean) * rstd * gv.y + bv.y;
    float o2 = (v.z - mean) * rstd * gv.z + bv.z;
    float o3 = (v.w - mean) * rstd * gv.w + bv.w;
    uint32_t h01, l01, h23, l23;
    split2(o0, o1, h01, l01);
    split2(o2, o3, h23, l23);
    size_t base = (size_t)row * D_ + tid * 4;
    *(uint2*)(outH + base) = make_uint2(h01, h23);
    *(uint2*)(outL + base) = make_uint2(l01, l23);
}

// ---------------- RoPE -> split bf16 ----------------
__global__ void rope_split(const float* __restrict__ q,
                           bf16* __restrict__ oh, bf16* __restrict__ ol) {
    int idx = blockIdx.x * blockDim.x + threadIdx.x;
    int i = idx & 31;
    int h = (idx >> 5) & (H_ - 1);
    int r = idx >> 9;
    int s = r >> 2;
    float inv = expf(-0.28782313662425572f * (float)i);
    float ang = (float)s * inv;
    float c, sn;
    sincosf(ang, &sn, &c);
    size_t base = (size_t)r * D_ + h * HD_ + i;
    float x1 = q[base], x2 = q[base + 32];
    float y1 = x1 * c - x2 * sn;
    float y2 = x2 * c + x1 * sn;
    bf16 h1 = __float2bfloat16(y1);
    bf16 h2 = __float2bfloat16(y2);
    oh[base]      = h1;
    oh[base + 32] = h2;
    ol[base]      = __float2bfloat16(y1 - __bfloat162float(h1));
    ol[base + 32] = __float2bfloat16(y2 - __bfloat162float(h2));
}

// ---------------- x += dur[r]*Wdur[c] + bdur[c] ----------------
__global__ void adddur_kernel(float* __restrict__ x, const float* __restrict__ dur,
                              const float* __restrict__ wd, const float* __restrict__ bd) {
    int idx = blockIdx.x * blockDim.x + threadIdx.x;
    int r = idx >> 10, c = idx & 1023;
    x[idx] += dur[r] * wd[c] + bd[c];
}

// ---------------- masked softmax -> split bf16 probs ----------------
__global__ __launch_bounds__(128) void softmax_kernel(
    const float* __restrict__ scores, const void* __restrict__ maskp,
    bf16* __restrict__ ph, bf16* __restrict__ pl)
{
    int row = blockIdx.x;
    int bh  = row >> 9;
    int b   = bh >> 4;
    const float* p = scores + (size_t)row * S_;
    int mode = g_mask_mode;
    const unsigned char* mu8 = (const unsigned char*)maskp;
    const int*   mi = (const int*)maskp;
    const float* mf = (const float*)maskp;
    int tid = threadIdx.x;
    float v[4];
    float mx = -1e30f;
#pragma unroll
    for (int kq = 0; kq < 4; kq++) {
        int j = tid + kq * 128;
        float s = p[j] * 0.125f;
        bool m;
        if (mode == 1)      m = mi[b * S_ + j] != 0;
        else if (mode == 2) m = mf[b * S_ + j] != 0.f;
        else                m = mu8[b * S_ + j] != 0;
        v[kq] = m ? -1e30f : s;
        mx = fmaxf(mx, v[kq]);
    }
    __shared__ float red[128];
    red[tid] = mx; __syncthreads();
    for (int off = 64; off > 0; off >>= 1) {
        if (tid < off) red[tid] = fmaxf(red[tid], red[tid + off]);
        __syncthreads();
    }
    mx = red[0]; __syncthreads();
    float sum = 0.f;
#pragma unroll
    for (int kq = 0; kq < 4; kq++) { v[kq] = expf(v[kq] - mx); sum += v[kq]; }
    red[tid] = sum; __syncthreads();
    for (int off = 64; off > 0; off >>= 1) {
        if (tid < off) red[tid] += red[tid + off];
        __syncthreads();
    }
    float inv = 1.f / red[0];
    bf16* phr = ph + (size_t)row * S_;
    bf16* plr = pl + (size_t)row * S_;
#pragma unroll
    for (int kq = 0; kq < 4; kq++) {
        int j = tid + kq * 128;
        float w = v[kq] * inv;
        bf16 hh = __float2bfloat16(w);
        phr[j] = hh;
        plr[j] = __float2bfloat16(w - __bfloat162float(hh));
    }
}

// ---------------- host orchestration ----------------
extern "C" void kernel_launch(void* const* d_in, const int* in_sizes, int n_in,
                              void* d_out, int out_size)
{
    (void)in_sizes; (void)n_in; (void)out_size;
    const float* segments  = (const float*)d_in[0];
    const float* durations = (const float*)d_in[1];
    const void*  mask      = d_in[2];
    const float* Wproj = (const float*)d_in[3];
    const float* bproj = (const float*)d_in[4];
    const float* Wdur  = (const float*)d_in[5];
    const float* bdur  = (const float*)d_in[6];
    const float* ln1g  = (const float*)d_in[7];
    const float* ln1b  = (const float*)d_in[8];
    const float* Wq    = (const float*)d_in[9];
    const float* bq    = (const float*)d_in[10];
    const float* Wk    = (const float*)d_in[11];
    const float* bk    = (const float*)d_in[12];
    const float* Wv    = (const float*)d_in[13];
    const float* bv    = (const float*)d_in[14];
    const float* Wo    = (const float*)d_in[15];
    const float* bo    = (const float*)d_in[16];
    const float* ln2g  = (const float*)d_in[17];
    const float* ln2b  = (const float*)d_in[18];
    const float* W1    = (const float*)d_in[19];
    const float* b1    = (const float*)d_in[20];
    const float* W2    = (const float*)d_in[21];
    const float* b2    = (const float*)d_in[22];
    float* x = (float*)d_out;

    bf16 *wqkvH, *wqkvL, *woH, *woL, *w1H, *w1L, *w2H, *w2L, *wpH, *wpL;
    bf16 *segH, *segL, *hH, *hL, *aH, *aL, *ffH, *ffL;
    bf16 *qh, *ql, *kh, *kl, *vh, *vl, *ph, *pl;
    float *bqkv, *qkv, *scores;
    cudaGetSymbolAddress((void**)&wqkvH, g_wqkv_h);
    cudaGetSymbolAddress((void**)&wqkvL, g_wqkv_l);
    cudaGetSymbolAddress((void**)&woH,   g_wo_h);
    cudaGetSymbolAddress((void**)&woL,   g_wo_l);
    cudaGetSymbolAddress((void**)&w1H,   g_w1_h);
    cudaGetSymbolAddress((void**)&w1L,   g_w1_l);
    cudaGetSymbolAddress((void**)&w2H,   g_w2_h);
    cudaGetSymbolAddress((void**)&w2L,   g_w2_l);
    cudaGetSymbolAddress((void**)&wpH,   g_wp_h);
    cudaGetSymbolAddress((void**)&wpL,   g_wp_l);
    cudaGetSymbolAddress((void**)&segH,  g_seg_h);
    cudaGetSymbolAddress((void**)&segL,  g_seg_l);
    cudaGetSymbolAddress((void**)&hH,    g_hh);
    cudaGetSymbolAddress((void**)&hL,    g_hl);
    cudaGetSymbolAddress((void**)&aH,    g_ah);
    cudaGetSymbolAddress((void**)&aL,    g_al);
    cudaGetSymbolAddress((void**)&ffH,   g_ffh);
    cudaGetSymbolAddress((void**)&ffL,   g_ffl);
    cudaGetSymbolAddress((void**)&bqkv,  g_bqkv);
    cudaGetSymbolAddress((void**)&qkv,   g_qkv);
    cudaGetSymbolAddress((void**)&scores, g_scores);
    cudaGetSymbolAddress((void**)&qh, g_qh);
    cudaGetSymbolAddress((void**)&ql, g_ql);
    cudaGetSymbolAddress((void**)&kh, g_kh);
    cudaGetSymbolAddress((void**)&kl, g_kl);
    cudaGetSymbolAddress((void**)&vh, g_vh);
    cudaGetSymbolAddress((void**)&vl, g_vl);
    cudaGetSymbolAddress((void**)&ph, g_ph);
    cudaGetSymbolAddress((void**)&pl, g_pl);

    cudaFuncSetAttribute(hmma2<0>, cudaFuncAttributeMaxDynamicSharedMemorySize, GEMM_SMEM);
    cudaFuncSetAttribute(hmma2<1>, cudaFuncAttributeMaxDynamicSharedMemorySize, GEMM_SMEM);
    cudaFuncSetAttribute(hmma2<2>, cudaFuncAttributeMaxDynamicSharedMemorySize, GEMM_SMEM);
    cudaFuncSetAttribute(scores_hmma, cudaFuncAttributeMaxDynamicSharedMemorySize, SC_SMEM);
    cudaFuncSetAttribute(attnv_hmma, cudaFuncAttributeMaxDynamicSharedMemorySize, AV_SMEM);

    detect_mask_kernel<<<1, 512>>>(mask);

    const int CT = 256;
    int nqkv = L_ * DD_;
    conv_split<<<(nqkv + CT - 1) / CT, CT>>>(Wq, wqkvH, wqkvL, nqkv, DD_, 3, 0);
    conv_split<<<(nqkv + CT - 1) / CT, CT>>>(Wk, wqkvH, wqkvL, nqkv, DD_, 3, 1);
    conv_split<<<(nqkv + CT - 1) / CT, CT>>>(Wv, wqkvH, wqkvL, nqkv, DD_, 3, 2);
    conv_split<<<(nqkv + CT - 1) / CT, CT>>>(Wo, woH, woL, nqkv, 1, 1, 0);
    int nff = L_ * DF_;
    conv_split<<<(nff + CT - 1) / CT, CT>>>(W1, w1H, w1L, nff, 1, 1, 0);
    conv_split<<<(nff + CT - 1) / CT, CT>>>(W2, w2H, w2L, nff, 1, 1, 0);
    conv_split<<<(DIN_ * D_ + CT - 1) / CT, CT>>>(Wproj, wpH, wpL, DIN_ * D_, 1, 1, 0);
    conv_split<<<(SB_ * DIN_ + CT - 1) / CT, CT>>>(segments, segH, segL, SB_ * DIN_, 1, 1, 0);
    int nb = L_ * D_;
    map_bias<<<(nb + CT - 1) / CT, CT>>>(bq, bqkv, nb, D_, 3, 0);
    map_bias<<<(nb + CT - 1) / CT, CT>>>(bk, bqkv, nb, D_, 3, 1);
    map_bias<<<(nb + CT - 1) / CT, CT>>>(bv, bqkv, nb, D_, 3, 2);

    dim3 gD(D_ / 128, SB_ / 128);
    dim3 gQKV(D_ / 128, SB_ / 128, 3);
    dim3 gF(F_ / 128, SB_ / 128);

    hmma2<0><<<gD, 256, GEMM_SMEM>>>(segH, segL, wpH, wpL, bproj, x, nullptr, nullptr,
                                     SB_, D_, DIN_, 0, 0, 0);
    adddur_kernel<<<(SB_ * D_) / 256, 256>>>(x, durations, Wdur, bdur);

    float* q = qkv;
    float* k = qkv + (size_t)SB_ * D_;
    float* v = qkv + 2 * (size_t)SB_ * D_;

    for (int l = 0; l < L_; l++) {
        ln_kernel<<<SB_, 256>>>(x, ln1g + (size_t)l * D_, ln1b + (size_t)l * D_, hH, hL);
        hmma2<0><<<gQKV, 256, GEMM_SMEM>>>(hH, hL,
            wqkvH + (size_t)l * 3 * DD_, wqkvL + (size_t)l * 3 * DD_,
            bqkv + (size_t)l * 3 * D_, qkv, nullptr, nullptr,
            SB_, D_, D_, DD_, D_, (long long)SB_ * D_);
        rope_split<<<(SB_ * H_ * 32) / 256, 256>>>(q, qh, ql);
        rope_split<<<(SB_ * H_ * 32) / 256, 256>>>(k, kh, kl);
        conv_split<<<(SB_ * D_ + CT - 1) / CT, CT>>>(v, vh, vl, SB_ * D_, 1, 1, 0);
        scores_hmma<<<dim3(4, 4, BH_), 256, SC_SMEM>>>(qh, ql, kh, kl, scores);
        softmax_kernel<<<BH_ * S_, 128>>>(scores, mask, ph, pl);
        attnv_hmma<<<dim3(4, BH_), 256, AV_SMEM>>>(ph, pl, vh, vl, aH, aL);
        hmma2<1><<<gD, 256, GEMM_SMEM>>>(aH, aL,
            woH + (size_t)l * DD_, woL + (size_t)l * DD_,
            bo + (size_t)l * D_, x, nullptr, nullptr, SB_, D_, D_, 0, 0, 0);
        ln_kernel<<<SB_, 256>>>(x, ln2g + (size_t)l * D_, ln2b + (size_t)l * D_, hH, hL);
        hmma2<2><<<gF, 256, GEMM_SMEM>>>(hH, hL,
            w1H + (size_t)l * DF_, w1L + (size_t)l * DF_,
            b1 + (size_t)l * F_, nullptr, ffH, ffL, SB_, F_, D_, 0, 0, 0);
        hmma2<1><<<gD, 256, GEMM_SMEM>>>(ffH, ffL,
            w2H + (size_t)l * DF_, w2L + (size_t)l * DF_,
            b2 + (size_t)l * D_, x, nullptr, nullptr, SB_, D_, F_, 0, 0, 0);
    }
}

// round 9
// speedup vs baseline: 3.1001x; 1.1399x over previous
#include <cuda_runtime.h>
#include <cuda_bf16.h>
#include <math.h>
#include <stdint.h>

#define L_   12
#define S_   512
#define B_   4
#define DIN_ 768
#define D_   1024
#define H_   16
#define F_   4096
#define HD_  64
#define SB_  2048
#define BH_  (B_*H_)
#define DD_  (D_*D_)
#define DF_  (D_*F_)

typedef __nv_bfloat16 bf16;

// ---------------- persistent scratch (device globals) ----------------
__device__ __align__(16) bf16 g_wqkv_h[(size_t)L_*3*DD_];
__device__ __align__(16) bf16 g_wqkv_l[(size_t)L_*3*DD_];
__device__ __align__(16) bf16 g_wo_h  [(size_t)L_*DD_];
__device__ __align__(16) bf16 g_wo_l  [(size_t)L_*DD_];
__device__ __align__(16) bf16 g_w1_h  [(size_t)L_*DF_];
__device__ __align__(16) bf16 g_w1_l  [(size_t)L_*DF_];
__device__ __align__(16) bf16 g_w2_h  [(size_t)L_*DF_];
__device__ __align__(16) bf16 g_w2_l  [(size_t)L_*DF_];
__device__ __align__(16) bf16 g_wp_h  [DIN_*D_];
__device__ __align__(16) bf16 g_wp_l  [DIN_*D_];
__device__ float g_bqkv[L_*3*D_];
__device__ __align__(16) bf16 g_seg_h[SB_*DIN_];
__device__ __align__(16) bf16 g_seg_l[SB_*DIN_];
__device__ __align__(16) bf16 g_hh[SB_*D_];
__device__ __align__(16) bf16 g_hl[SB_*D_];
__device__ __align__(16) bf16 g_ah[SB_*D_];
__device__ __align__(16) bf16 g_al[SB_*D_];
__device__ __align__(16) bf16 g_ffh[(size_t)SB_*F_];
__device__ __align__(16) bf16 g_ffl[(size_t)SB_*F_];
__device__ __align__(16) bf16 g_qh[SB_*D_];
__device__ __align__(16) bf16 g_ql[SB_*D_];
__device__ __align__(16) bf16 g_kh[SB_*D_];
__device__ __align__(16) bf16 g_kl[SB_*D_];
__device__ __align__(16) bf16 g_vh[SB_*D_];
__device__ __align__(16) bf16 g_vl[SB_*D_];
__device__ unsigned char g_mask8[B_*S_];
__device__ int   g_mask_mode;

// ============================================================================
// helpers
// ============================================================================
__device__ __forceinline__ uint32_t smem_u32(const void* p) {
    uint32_t a;
    asm("{ .reg .u64 t; cvta.to.shared.u64 t, %1; cvt.u32.u64 %0, t; }"
        : "=r"(a) : "l"(p));
    return a;
}
__device__ __forceinline__ void ldsm4(uint32_t* r, uint32_t addr) {
    asm volatile("ldmatrix.sync.aligned.m8n8.x4.shared.b16 {%0,%1,%2,%3}, [%4];"
                 : "=r"(r[0]), "=r"(r[1]), "=r"(r[2]), "=r"(r[3]) : "r"(addr));
}
__device__ __forceinline__ void ldsm4t(uint32_t* r, uint32_t addr) {
    asm volatile("ldmatrix.sync.aligned.m8n8.x4.trans.shared.b16 {%0,%1,%2,%3}, [%4];"
                 : "=r"(r[0]), "=r"(r[1]), "=r"(r[2]), "=r"(r[3]) : "r"(addr));
}
__device__ __forceinline__ void mma16816(float* d, const uint32_t* a, const uint32_t* b) {
    asm volatile(
        "mma.sync.aligned.m16n8k16.row.col.f32.bf16.bf16.f32 "
        "{%0,%1,%2,%3}, {%4,%5,%6,%7}, {%8,%9}, {%0,%1,%2,%3};"
        : "+f"(d[0]), "+f"(d[1]), "+f"(d[2]), "+f"(d[3])
        : "r"(a[0]), "r"(a[1]), "r"(a[2]), "r"(a[3]), "r"(b[0]), "r"(b[1]));
}
#define CP_ASYNC(dst, src) \
    asm volatile("cp.async.cg.shared.global [%0], [%1], 16;" :: "r"(dst), "l"(src))
#define CP_COMMIT() asm volatile("cp.async.commit_group;")
#define CP_WAIT(n)  asm volatile("cp.async.wait_group %0;" :: "n"(n))

__device__ __forceinline__ void split2(float v0, float v1, uint32_t& hi, uint32_t& lo) {
    __nv_bfloat162 h = __floats2bfloat162_rn(v0, v1);
    __nv_bfloat162 l = __floats2bfloat162_rn(v0 - __bfloat162float(h.x),
                                             v1 - __bfloat162float(h.y));
    hi = *(uint32_t*)&h; lo = *(uint32_t*)&l;
}

// ============================================================================
// conversions (vectorized x4)
// ============================================================================
__global__ void conv_split4(const float4* __restrict__ src, bf16* __restrict__ dh,
                            bf16* __restrict__ dl, int n4, int inner4, int gm, int go) {
    int i = blockIdx.x * blockDim.x + threadIdx.x;
    if (i >= n4) return;
    float4 v = src[i];
    size_t d = ((size_t)(i / inner4) * inner4 * gm + (size_t)go * inner4 + (i % inner4)) * 4;
    uint32_t h01, l01, h23, l23;
    split2(v.x, v.y, h01, l01);
    split2(v.z, v.w, h23, l23);
    *(uint2*)(dh + d) = make_uint2(h01, h23);
    *(uint2*)(dl + d) = make_uint2(l01, l23);
}
__global__ void map_bias(const float* __restrict__ src, float* __restrict__ dst,
                         int n, int inner, int gm, int go) {
    int i = blockIdx.x * blockDim.x + threadIdx.x;
    if (i >= n) return;
    dst[(size_t)(i / inner) * inner * gm + (size_t)go * inner + (i % inner)] = src[i];
}

// ---------------- mask: detect dtype, canonicalize to u8 ----------------
__global__ void detect_mask_kernel(const void* m) {
    __shared__ int flags[2];
    if (threadIdx.x == 0) { flags[0] = 0; flags[1] = 0; }
    __syncthreads();
    unsigned v = ((const unsigned*)m)[threadIdx.x];
    if (v > 1u) flags[0] = 1;
    if (v != 0u && v != 0x3F800000u) flags[1] = 1;
    __syncthreads();
    if (threadIdx.x == 0)
        g_mask_mode = (!flags[0]) ? 1 : ((!flags[1]) ? 2 : 0);
}
__global__ void mask8_kernel(const void* m) {
    int i = blockIdx.x * blockDim.x + threadIdx.x;   // B_*S_ = 2048
    int mode = g_mask_mode;
    unsigned char r;
    if (mode == 1)      r = ((const int*)m)[i] != 0;
    else if (mode == 2) r = ((const float*)m)[i] != 0.f;
    else                r = ((const unsigned char*)m)[i] != 0;
    g_mask8[i] = r;
}

// ============================================================================
// split-bf16 HMMA GEMM
// MODE 0: C = acc+bias     MODE 1: C += acc+bias
// MODE 2: CH/CL = split(gelu(acc+bias))
// MODE 3: QKV fused epilogue: z=0 rope->q, z=1 rope->k, z=2 plain->v (split bf16)
// ============================================================================
#define A_STRIDE   80
#define B_STRIDE   272
#define AH_OFF     0
#define AL_OFF     10240
#define BH_OFF     20480
#define BL_OFF     29184
#define STAGE_B    37888
#define GEMM_SMEM  (2*STAGE_B)

__device__ __forceinline__ void load_stage(
    const bf16* __restrict__ AH, const bf16* __restrict__ AL,
    const bf16* __restrict__ WH, const bf16* __restrict__ WL,
    int K, int N, int rowBase, int colBase, int ck, uint32_t st, int tid)
{
#pragma unroll
    for (int t = 0; t < 4; t++) {
        int idx = tid + t * 256;
        int tile = idx >> 9;
        int r = (idx >> 2) & 127;
        int c16 = idx & 3;
        const bf16* src = (tile ? AL : AH) + (size_t)(rowBase + r) * K + ck + c16 * 8;
        uint32_t dst = st + (tile ? AL_OFF : AH_OFF) + r * A_STRIDE + c16 * 16;
        CP_ASYNC(dst, src);
    }
#pragma unroll
    for (int t = 0; t < 4; t++) {
        int idx = tid + t * 256;
        int tile = idx >> 9;
        int r = (idx >> 4) & 31;
        int c16 = idx & 15;
        const bf16* src = (tile ? WL : WH) + (size_t)(ck + r) * N + colBase + c16 * 8;
        uint32_t dst = st + (tile ? BL_OFF : BH_OFF) + r * B_STRIDE + c16 * 16;
        CP_ASYNC(dst, src);
    }
}

template<int MODE>
__global__ void __launch_bounds__(256, 2) hmma2(
    const bf16* __restrict__ AH, const bf16* __restrict__ AL,
    const bf16* __restrict__ WH, const bf16* __restrict__ WL,
    const float* __restrict__ bias, float* __restrict__ C,
    bf16* __restrict__ CH, bf16* __restrict__ CL,
    bf16* __restrict__ o1h, bf16* __restrict__ o1l,
    bf16* __restrict__ o2h, bf16* __restrict__ o2l,
    int M, int N, int K, long long Wz, long long bz, long long Cz)
{
    extern __shared__ char smem[];
    const int z = blockIdx.z;
    WH += (size_t)z * Wz; WL += (size_t)z * Wz; bias += (size_t)z * bz;
    float* Cp = C + (size_t)z * Cz;

    const int tid  = threadIdx.x;
    const int lane = tid & 31;
    const int wid  = tid >> 5;
    const int m0   = (wid & 3) << 5;
    const int n0w  = (wid >> 2) << 6;
    const int rowBase = blockIdx.y << 7;
    const int colBase = blockIdx.x << 7;
    const int NC = K >> 5;

    uint32_t sbase = smem_u32(smem);

    float acc[2][8][4];
#pragma unroll
    for (int a = 0; a < 2; a++)
#pragma unroll
        for (int b = 0; b < 8; b++)
#pragma unroll
            for (int c = 0; c < 4; c++) acc[a][b][c] = 0.f;

    load_stage(AH, AL, WH, WL, K, N, rowBase, colBase, 0, sbase, tid);
    CP_COMMIT();
    load_stage(AH, AL, WH, WL, K, N, rowBase, colBase, 32, sbase + STAGE_B, tid);
    CP_COMMIT();
    CP_WAIT(1);
    __syncthreads();

    const int arow = lane & 15;
    const int aoff = (lane >> 4) << 4;

    for (int c = 0; c < NC; c++) {
        uint32_t cur = sbase + (c & 1) * STAGE_B;
#pragma unroll
        for (int ks = 0; ks < 32; ks += 16) {
            uint32_t ah[2][4], al[2][4];
#pragma unroll
            for (int mt = 0; mt < 2; mt++) {
                uint32_t ad = cur + (uint32_t)((m0 + mt * 16 + arow) * A_STRIDE + ks * 2 + aoff);
                ldsm4(ah[mt], ad);
                ldsm4(al[mt], ad + AL_OFF);
            }
#pragma unroll
            for (int np = 0; np < 4; np++) {
                uint32_t bh[4], bl[4];
                uint32_t bd = cur + BH_OFF +
                    (uint32_t)((ks + arow) * B_STRIDE + ((n0w + np * 16) << 1) + aoff);
                ldsm4t(bh, bd);
                ldsm4t(bl, bd + (BL_OFF - BH_OFF));
#pragma unroll
                for (int mt = 0; mt < 2; mt++)
#pragma unroll
                    for (int e = 0; e < 2; e++) {
                        uint32_t bfh[2] = { bh[2 * e], bh[2 * e + 1] };
                        uint32_t bfl[2] = { bl[2 * e], bl[2 * e + 1] };
                        float* d = acc[mt][np * 2 + e];
                        mma16816(d, ah[mt], bfh);
                        mma16816(d, al[mt], bfh);
                        mma16816(d, ah[mt], bfl);
                    }
            }
        }
        __syncthreads();
        if (c + 2 < NC) {
            load_stage(AH, AL, WH, WL, K, N, rowBase, colBase, (c + 2) << 5,
                       sbase + (c & 1) * STAGE_B, tid);
            CP_COMMIT();
            CP_WAIT(1);
        } else {
            CP_WAIT(0);
        }
        __syncthreads();
    }

    // ---- epilogue ----
    if (MODE == 3) {
        bf16* dh = (z == 0) ? CH : (z == 1) ? o1h : o2h;
        bf16* dl = (z == 0) ? CL : (z == 1) ? o1l : o2l;
#pragma unroll
        for (int mt = 0; mt < 2; mt++) {
#pragma unroll
            for (int half = 0; half < 2; half++) {
                const int row = rowBase + m0 + mt * 16 + (lane >> 2) + half * 8;
                const int s = row >> 2;
                if (z < 2) {
#pragma unroll
                    for (int nt = 0; nt < 4; nt++) {
                        const int c0 = colBase + n0w + (nt << 3) + ((lane & 3) << 1);
                        float v0 = acc[mt][nt][half * 2 + 0] + bias[c0];
                        float v1 = acc[mt][nt][half * 2 + 1] + bias[c0 + 1];
                        float w0 = acc[mt][nt + 4][half * 2 + 0] + bias[c0 + 32];
                        float w1 = acc[mt][nt + 4][half * 2 + 1] + bias[c0 + 33];
                        int i0 = c0 & 63;
                        float th0 = (float)s * expf(-0.28782313662425572f * (float)i0);
                        float th1 = (float)s * expf(-0.28782313662425572f * (float)(i0 + 1));
                        float c0s, s0s, c1s, s1s;
                        sincosf(th0, &s0s, &c0s);
                        sincosf(th1, &s1s, &c1s);
                        float y0 = v0 * c0s - w0 * s0s, zz0 = w0 * c0s + v0 * s0s;
                        float y1 = v1 * c1s - w1 * s1s, zz1 = w1 * c1s + v1 * s1s;
                        uint32_t hi, lo;
                        split2(y0, y1, hi, lo);
                        *(uint32_t*)(dh + (size_t)row * D_ + c0) = hi;
                        *(uint32_t*)(dl + (size_t)row * D_ + c0) = lo;
                        split2(zz0, zz1, hi, lo);
                        *(uint32_t*)(dh + (size_t)row * D_ + c0 + 32) = hi;
                        *(uint32_t*)(dl + (size_t)row * D_ + c0 + 32) = lo;
                    }
                } else {
#pragma unroll
                    for (int nt = 0; nt < 8; nt++) {
                        const int c0 = colBase + n0w + (nt << 3) + ((lane & 3) << 1);
                        float v0 = acc[mt][nt][half * 2 + 0] + bias[c0];
                        float v1 = acc[mt][nt][half * 2 + 1] + bias[c0 + 1];
                        uint32_t hi, lo;
                        split2(v0, v1, hi, lo);
                        *(uint32_t*)(dh + (size_t)row * D_ + c0) = hi;
                        *(uint32_t*)(dl + (size_t)row * D_ + c0) = lo;
                    }
                }
            }
        }
        return;
    }

#pragma unroll
    for (int mt = 0; mt < 2; mt++) {
        const int r0 = rowBase + m0 + mt * 16 + (lane >> 2);
#pragma unroll
        for (int nt = 0; nt < 8; nt++) {
            const int c0 = colBase + n0w + nt * 8 + ((lane & 3) << 1);
            float* d = acc[mt][nt];
            float b0 = bias[c0], b1 = bias[c0 + 1];
#pragma unroll
            for (int half = 0; half < 2; half++) {
                const int row = r0 + half * 8;
                float v0 = d[half * 2 + 0] + b0;
                float v1 = d[half * 2 + 1] + b1;
                if (MODE == 0) {
                    float* out = Cp + (size_t)row * N + c0;
                    out[0] = v0; out[1] = v1;
                } else if (MODE == 1) {
                    float* out = Cp + (size_t)row * N + c0;
                    out[0] += v0; out[1] += v1;
                } else {
                    float g0 = 0.5f * v0 * (1.f + erff(v0 * 0.70710678118654752f));
                    float g1 = 0.5f * v1 * (1.f + erff(v1 * 0.70710678118654752f));
                    uint32_t hi, lo;
                    split2(g0, g1, hi, lo);
                    *(uint32_t*)(CH + (size_t)row * N + c0) = hi;
                    *(uint32_t*)(CL + (size_t)row * N + c0) = lo;
                }
            }
        }
    }
}

// ============================================================================
// Flash attention: per (b,h,q-tile 128) fused QK^T -> masked online softmax -> PV
// smem: Qh,Ql [128][64] + 2 KV buffers (Kh,Kl,Vh,Vl each [128][64])
// ============================================================================
#define FA_STRIDE 144
#define FA_TILE   18432
#define FA_SMEM   (10*FA_TILE)   // 184320

__device__ __forceinline__ void fa_kv_load(
    const bf16* __restrict__ kh, const bf16* __restrict__ kl,
    const bf16* __restrict__ vh, const bf16* __restrict__ vl,
    size_t hoff, int krow0, uint32_t dst, int tid)
{
#pragma unroll
    for (int t = 0; t < 16; t++) {
        int idx = tid + t * 256;
        int tile = idx >> 10, rem = idx & 1023;
        int r = rem >> 3, c = rem & 7;
        const bf16* base = (tile == 0) ? kh : (tile == 1) ? kl : (tile == 2) ? vh : vl;
        const bf16* src = base + hoff + (size_t)(krow0 + r) * (B_ * D_) + c * 8;
        CP_ASYNC(dst + tile * FA_TILE + r * FA_STRIDE + c * 16, src);
    }
}

__global__ void __launch_bounds__(256, 1) flash_attn(
    const bf16* __restrict__ qh, const bf16* __restrict__ ql,
    const bf16* __restrict__ kh, const bf16* __restrict__ kl,
    const bf16* __restrict__ vh, const bf16* __restrict__ vl,
    const unsigned char* __restrict__ mask8,
    bf16* __restrict__ aH, bf16* __restrict__ aL)
{
    extern __shared__ char smem[];
    const int bh = blockIdx.y;
    const int b = bh >> 4, h = bh & 15;
    const int q0 = blockIdx.x << 7;
    const int tid = threadIdx.x, lane = tid & 31, wid = tid >> 5;
    const int m0 = wid << 4;
    const size_t hoff = (size_t)b * D_ + h * HD_;
    uint32_t sb = smem_u32(smem);
    const uint32_t kv0 = sb + 2 * FA_TILE;
    const uint32_t kv1 = sb + 6 * FA_TILE;

    // Q tiles + KV kt=0 (group A)
#pragma unroll
    for (int t = 0; t < 8; t++) {
        int idx = tid + t * 256;
        int tile = idx >> 10, rem = idx & 1023;
        int r = rem >> 3, c = rem & 7;
        const bf16* src = (tile ? ql : qh) + hoff + (size_t)(q0 + r) * (B_ * D_) + c * 8;
        CP_ASYNC(sb + tile * FA_TILE + r * FA_STRIDE + c * 16, src);
    }
    fa_kv_load(kh, kl, vh, vl, hoff, 0, kv0, tid);
    CP_COMMIT();
    fa_kv_load(kh, kl, vh, vl, hoff, 128, kv1, tid);
    CP_COMMIT();
    CP_WAIT(1);
    __syncthreads();

    float oacc[8][4];
#pragma unroll
    for (int i = 0; i < 8; i++)
#pragma unroll
        for (int j = 0; j < 4; j++) oacc[i][j] = 0.f;
    float mr0 = -1e30f, mr1 = -1e30f, l0 = 0.f, l1 = 0.f;

    const int arow = lane & 15;
    const int aoff = (lane >> 4) << 4;
    const unsigned char* mrow = mask8 + b * S_;

    for (int kt = 0; kt < 4; kt++) {
        const uint32_t kv = (kt & 1) ? kv1 : kv0;
        float sacc[16][4];
#pragma unroll
        for (int i = 0; i < 16; i++)
#pragma unroll
            for (int j = 0; j < 4; j++) sacc[i][j] = 0.f;

        // S = Q K^T (3-term split)
#pragma unroll
        for (int kc = 0; kc < 4; kc++) {
            uint32_t qa = sb + (uint32_t)((m0 + arow) * FA_STRIDE + kc * 32 + aoff);
            uint32_t qhf[4], qlf[4];
            ldsm4(qhf, qa);
            ldsm4(qlf, qa + FA_TILE);
#pragma unroll
            for (int ng = 0; ng < 8; ng++) {
                uint32_t bhf[4], blf[4];
                uint32_t ka = kv + (uint32_t)((ng * 16 + arow) * FA_STRIDE + kc * 32 + aoff);
                ldsm4(bhf, ka);
                ldsm4(blf, ka + FA_TILE);
#pragma unroll
                for (int e = 0; e < 2; e++) {
                    uint32_t bh2[2] = { bhf[e], bhf[e + 2] };
                    uint32_t bl2[2] = { blf[e], blf[e + 2] };
                    float* d = sacc[ng * 2 + e];
                    mma16816(d, qhf, bh2);
                    mma16816(d, qlf, bh2);
                    mma16816(d, qhf, bl2);
                }
            }
        }

        // mask + scale + row max
        float mx0 = -1e30f, mx1 = -1e30f;
#pragma unroll
        for (int nt = 0; nt < 16; nt++) {
#pragma unroll
            for (int u = 0; u < 2; u++) {
                int col = (kt << 7) + (nt << 3) + ((lane & 3) << 1) + u;
                bool msk = mrow[col] != 0;
                float v0 = msk ? -1e30f : sacc[nt][u] * 0.125f;
                float v1 = msk ? -1e30f : sacc[nt][2 + u] * 0.125f;
                sacc[nt][u] = v0; sacc[nt][2 + u] = v1;
                mx0 = fmaxf(mx0, v0); mx1 = fmaxf(mx1, v1);
            }
        }
        mx0 = fmaxf(mx0, __shfl_xor_sync(0xFFFFFFFFu, mx0, 1));
        mx0 = fmaxf(mx0, __shfl_xor_sync(0xFFFFFFFFu, mx0, 2));
        mx1 = fmaxf(mx1, __shfl_xor_sync(0xFFFFFFFFu, mx1, 1));
        mx1 = fmaxf(mx1, __shfl_xor_sync(0xFFFFFFFFu, mx1, 2));
        float mn0 = fmaxf(mr0, mx0), mn1 = fmaxf(mr1, mx1);
        float al0 = __expf(mr0 - mn0), al1 = __expf(mr1 - mn1);
        mr0 = mn0; mr1 = mn1;

        float s0 = 0.f, s1 = 0.f;
#pragma unroll
        for (int nt = 0; nt < 16; nt++) {
            float p0 = __expf(sacc[nt][0] - mn0);
            float p1 = __expf(sacc[nt][1] - mn0);
            float p2 = __expf(sacc[nt][2] - mn1);
            float p3 = __expf(sacc[nt][3] - mn1);
            sacc[nt][0] = p0; sacc[nt][1] = p1; sacc[nt][2] = p2; sacc[nt][3] = p3;
            s0 += p0 + p1; s1 += p2 + p3;
        }
        s0 += __shfl_xor_sync(0xFFFFFFFFu, s0, 1);
        s0 += __shfl_xor_sync(0xFFFFFFFFu, s0, 2);
        s1 += __shfl_xor_sync(0xFFFFFFFFu, s1, 1);
        s1 += __shfl_xor_sync(0xFFFFFFFFu, s1, 2);
        l0 = l0 * al0 + s0;
        l1 = l1 * al1 + s1;
#pragma unroll
        for (int nt = 0; nt < 8; nt++) {
            oacc[nt][0] *= al0; oacc[nt][1] *= al0;
            oacc[nt][2] *= al1; oacc[nt][3] *= al1;
        }

        // O += P V (3-term split; P fragments from sacc, C-frag == A-frag)
#pragma unroll
        for (int kc2 = 0; kc2 < 8; kc2++) {
            uint32_t pa_h[4], pa_l[4];
            split2(sacc[2 * kc2][0],     sacc[2 * kc2][1],     pa_h[0], pa_l[0]);
            split2(sacc[2 * kc2][2],     sacc[2 * kc2][3],     pa_h[1], pa_l[1]);
            split2(sacc[2 * kc2 + 1][0], sacc[2 * kc2 + 1][1], pa_h[2], pa_l[2]);
            split2(sacc[2 * kc2 + 1][2], sacc[2 * kc2 + 1][3], pa_h[3], pa_l[3]);
#pragma unroll
            for (int ng = 0; ng < 4; ng++) {
                uint32_t bhf[4], blf[4];
                uint32_t va = kv + 2 * FA_TILE +
                    (uint32_t)((kc2 * 16 + arow) * FA_STRIDE + ng * 32 + aoff);
                ldsm4t(bhf, va);
                ldsm4t(blf, va + FA_TILE);
#pragma unroll
                for (int e = 0; e < 2; e++) {
                    uint32_t bh2[2] = { bhf[2 * e], bhf[2 * e + 1] };
                    uint32_t bl2[2] = { blf[2 * e], blf[2 * e + 1] };
                    float* d = oacc[ng * 2 + e];
                    mma16816(d, pa_h, bh2);
                    mma16816(d, pa_l, bh2);
                    mma16816(d, pa_h, bl2);
                }
            }
        }

        __syncthreads();
        if (kt + 2 < 4) {
            fa_kv_load(kh, kl, vh, vl, hoff, (kt + 2) << 7, kv, tid);
            CP_COMMIT();
            CP_WAIT(1);
            __syncthreads();
        } else if (kt + 1 < 4) {
            CP_WAIT(0);
            __syncthreads();
        }
    }

    // epilogue: normalize and write split-bf16 attn [SB][D]
    float inv0 = 1.f / l0, inv1 = 1.f / l1;
    const int r0 = q0 + m0 + (lane >> 2);
#pragma unroll
    for (int nt = 0; nt < 8; nt++) {
        const int c0 = (nt << 3) + ((lane & 3) << 1);
        uint32_t hi, lo;
        split2(oacc[nt][0] * inv0, oacc[nt][1] * inv0, hi, lo);
        size_t a0 = hoff + (size_t)r0 * (B_ * D_) + c0;
        *(uint32_t*)(aH + a0) = hi;
        *(uint32_t*)(aL + a0) = lo;
        split2(oacc[nt][2] * inv1, oacc[nt][3] * inv1, hi, lo);
        size_t a1 = hoff + (size_t)(r0 + 8) * (B_ * D_) + c0;
        *(uint32_t*)(aH + a1) = hi;
        *(uint32_t*)(aL + a1) = lo;
    }
}

// ---------------- LayerNorm -> split bf16 ----------------
__global__ __launch_bounds__(256) void ln_kernel(
    const float* __restrict__ x, const float* __restrict__ g,
    const float* __restrict__ b, bf16* __restrict__ outH, bf16* __restrict__ outL)
{
    int row = blockIdx.x;
    int tid = threadIdx.x;
    const float* xr = x + (size_t)row * D_;
    float4 v = *(const float4*)(xr + tid * 4);
    float s  = v.x + v.y + v.z + v.w;
    float s2 = v.x * v.x + v.y * v.y + v.z * v.z + v.w * v.w;
    __shared__ float r1[256], r2[256];
    r1[tid] = s; r2[tid] = s2;
    __syncthreads();
    for (int off = 128; off > 0; off >>= 1) {
        if (tid < off) { r1[tid] += r1[tid + off]; r2[tid] += r2[tid + off]; }
        __syncthreads();
    }
    float mean = r1[0] * (1.f / D_);
    float var  = r2[0] * (1.f / D_) - mean * mean;
    float rstd = rsqrtf(var + 1e-5f);
    float4 gv = *(const float4*)(g + tid * 4);
    float4 bv = *(const float4*)(b + tid * 4);
    float o0 = (v.x - mean) * rstd * gv.x + bv.x;
    float o1 = (v.y - mean) * rstd * gv.y + bv.y;
    float o2 = (v.z - mean) * rstd * gv.z + bv.z;
    float o3 = (v.w - mean) * rstd * gv.w + bv.w;
    uint32_t h01, l01, h23, l23;
    split2(o0, o1, h01, l01);
    split2(o2, o3, h23, l23);
    size_t base = (size_t)row * D_ + tid * 4;
    *(uint2*)(outH + base) = make_uint2(h01, h23);
    *(uint2*)(outL + base) = make_uint2(l01, l23);
}

// ---------------- x += dur[r]*Wdur[c] + bdur[c] ----------------
__global__ void adddur_kernel(float* __restrict__ x, const float* __restrict__ dur,
                              const float* __restrict__ wd, const float* __restrict__ bd) {
    int idx = blockIdx.x * blockDim.x + threadIdx.x;
    int r = idx >> 10, c = idx & 1023;
    x[idx] += dur[r] * wd[c] + bd[c];
}

// ---------------- host orchestration ----------------
extern "C" void kernel_launch(void* const* d_in, const int* in_sizes, int n_in,
                              void* d_out, int out_size)
{
    (void)in_sizes; (void)n_in; (void)out_size;
    const float* segments  = (const float*)d_in[0];
    const float* durations = (const float*)d_in[1];
    const void*  mask      = d_in[2];
    const float* Wproj = (const float*)d_in[3];
    const float* bproj = (const float*)d_in[4];
    const float* Wdur  = (const float*)d_in[5];
    const float* bdur  = (const float*)d_in[6];
    const float* ln1g  = (const float*)d_in[7];
    const float* ln1b  = (const float*)d_in[8];
    const float* Wq    = (const float*)d_in[9];
    const float* bq    = (const float*)d_in[10];
    const float* Wk    = (const float*)d_in[11];
    const float* bk    = (const float*)d_in[12];
    const float* Wv    = (const float*)d_in[13];
    const float* bv    = (const float*)d_in[14];
    const float* Wo    = (const float*)d_in[15];
    const float* bo    = (const float*)d_in[16];
    const float* ln2g  = (const float*)d_in[17];
    const float* ln2b  = (const float*)d_in[18];
    const float* W1    = (const float*)d_in[19];
    const float* b1    = (const float*)d_in[20];
    const float* W2    = (const float*)d_in[21];
    const float* b2    = (const float*)d_in[22];
    float* x = (float*)d_out;

    bf16 *wqkvH, *wqkvL, *woH, *woL, *w1H, *w1L, *w2H, *w2L, *wpH, *wpL;
    bf16 *segH, *segL, *hH, *hL, *aH, *aL, *ffH, *ffL;
    bf16 *qh, *ql, *kh, *kl, *vh, *vl;
    float *bqkv;
    unsigned char* mask8;
    cudaGetSymbolAddress((void**)&wqkvH, g_wqkv_h);
    cudaGetSymbolAddress((void**)&wqkvL, g_wqkv_l);
    cudaGetSymbolAddress((void**)&woH,   g_wo_h);
    cudaGetSymbolAddress((void**)&woL,   g_wo_l);
    cudaGetSymbolAddress((void**)&w1H,   g_w1_h);
    cudaGetSymbolAddress((void**)&w1L,   g_w1_l);
    cudaGetSymbolAddress((void**)&w2H,   g_w2_h);
    cudaGetSymbolAddress((void**)&w2L,   g_w2_l);
    cudaGetSymbolAddress((void**)&wpH,   g_wp_h);
    cudaGetSymbolAddress((void**)&wpL,   g_wp_l);
    cudaGetSymbolAddress((void**)&segH,  g_seg_h);
    cudaGetSymbolAddress((void**)&segL,  g_seg_l);
    cudaGetSymbolAddress((void**)&hH,    g_hh);
    cudaGetSymbolAddress((void**)&hL,    g_hl);
    cudaGetSymbolAddress((void**)&aH,    g_ah);
    cudaGetSymbolAddress((void**)&aL,    g_al);
    cudaGetSymbolAddress((void**)&ffH,   g_ffh);
    cudaGetSymbolAddress((void**)&ffL,   g_ffl);
    cudaGetSymbolAddress((void**)&bqkv,  g_bqkv);
    cudaGetSymbolAddress((void**)&qh, g_qh);
    cudaGetSymbolAddress((void**)&ql, g_ql);
    cudaGetSymbolAddress((void**)&kh, g_kh);
    cudaGetSymbolAddress((void**)&kl, g_kl);
    cudaGetSymbolAddress((void**)&vh, g_vh);
    cudaGetSymbolAddress((void**)&vl, g_vl);
    cudaGetSymbolAddress((void**)&mask8, g_mask8);

    cudaFuncSetAttribute(hmma2<0>, cudaFuncAttributeMaxDynamicSharedMemorySize, GEMM_SMEM);
    cudaFuncSetAttribute(hmma2<1>, cudaFuncAttributeMaxDynamicSharedMemorySize, GEMM_SMEM);
    cudaFuncSetAttribute(hmma2<2>, cudaFuncAttributeMaxDynamicSharedMemorySize, GEMM_SMEM);
    cudaFuncSetAttribute(hmma2<3>, cudaFuncAttributeMaxDynamicSharedMemorySize, GEMM_SMEM);
    cudaFuncSetAttribute(flash_attn, cudaFuncAttributeMaxDynamicSharedMemorySize, FA_SMEM);

    detect_mask_kernel<<<1, 512>>>(mask);
    mask8_kernel<<<8, 256>>>(mask);

    const int CT = 256;
    int n4;
    n4 = (L_ * DD_) / 4;
    conv_split4<<<(n4 + CT - 1) / CT, CT>>>((const float4*)Wq, wqkvH, wqkvL, n4, DD_ / 4, 3, 0);
    conv_split4<<<(n4 + CT - 1) / CT, CT>>>((const float4*)Wk, wqkvH, wqkvL, n4, DD_ / 4, 3, 1);
    conv_split4<<<(n4 + CT - 1) / CT, CT>>>((const float4*)Wv, wqkvH, wqkvL, n4, DD_ / 4, 3, 2);
    conv_split4<<<(n4 + CT - 1) / CT, CT>>>((const float4*)Wo, woH, woL, n4, 1, 1, 0);
    n4 = (L_ * DF_) / 4;
    conv_split4<<<(n4 + CT - 1) / CT, CT>>>((const float4*)W1, w1H, w1L, n4, 1, 1, 0);
    conv_split4<<<(n4 + CT - 1) / CT, CT>>>((const float4*)W2, w2H, w2L, n4, 1, 1, 0);
    n4 = (DIN_ * D_) / 4;
    conv_split4<<<(n4 + CT - 1) / CT, CT>>>((const float4*)Wproj, wpH, wpL, n4, 1, 1, 0);
    n4 = (SB_ * DIN_) / 4;
    conv_split4<<<(n4 + CT - 1) / CT, CT>>>((const float4*)segments, segH, segL, n4, 1, 1, 0);
    int nb = L_ * D_;
    map_bias<<<(nb + CT - 1) / CT, CT>>>(bq, bqkv, nb, D_, 3, 0);
    map_bias<<<(nb + CT - 1) / CT, CT>>>(bk, bqkv, nb, D_, 3, 1);
    map_bias<<<(nb + CT - 1) / CT, CT>>>(bv, bqkv, nb, D_, 3, 2);

    dim3 gD(D_ / 128, SB_ / 128);
    dim3 gQKV(D_ / 128, SB_ / 128, 3);
    dim3 gF(F_ / 128, SB_ / 128);

    hmma2<0><<<gD, 256, GEMM_SMEM>>>(segH, segL, wpH, wpL, bproj, x,
        nullptr, nullptr, nullptr, nullptr, nullptr, nullptr, SB_, D_, DIN_, 0, 0, 0);
    adddur_kernel<<<(SB_ * D_) / 256, 256>>>(x, durations, Wdur, bdur);

    for (int l = 0; l < L_; l++) {
        ln_kernel<<<SB_, 256>>>(x, ln1g + (size_t)l * D_, ln1b + (size_t)l * D_, hH, hL);
        hmma2<3><<<gQKV, 256, GEMM_SMEM>>>(hH, hL,
            wqkvH + (size_t)l * 3 * DD_, wqkvL + (size_t)l * 3 * DD_,
            bqkv + (size_t)l * 3 * D_, nullptr,
            qh, ql, kh, kl, vh, vl,
            SB_, D_, D_, DD_, D_, 0);
        flash_attn<<<dim3(4, BH_), 256, FA_SMEM>>>(qh, ql, kh, kl, vh, vl, mask8, aH, aL);
        hmma2<1><<<gD, 256, GEMM_SMEM>>>(aH, aL,
            woH + (size_t)l * DD_, woL + (size_t)l * DD_,
            bo + (size_t)l * D_, x,
            nullptr, nullptr, nullptr, nullptr, nullptr, nullptr, SB_, D_, D_, 0, 0, 0);
        ln_kernel<<<SB_, 256>>>(x, ln2g + (size_t)l * D_, ln2b + (size_t)l * D_, hH, hL);
        hmma2<2><<<gF, 256, GEMM_SMEM>>>(hH, hL,
            w1H + (size_t)l * DF_, w1L + (size_t)l * DF_,
            b1 + (size_t)l * F_, nullptr,
            ffH, ffL, nullptr, nullptr, nullptr, nullptr, SB_, F_, D_, 0, 0, 0);
        hmma2<1><<<gD, 256, GEMM_SMEM>>>(ffH, ffL,
            w2H + (size_t)l * DF_, w2L + (size_t)l * DF_,
            b2 + (size_t)l * D_, x,
            nullptr, nullptr, nullptr, nullptr, nullptr, nullptr, SB_, D_, F_, 0, 0, 0);
    }
}

// round 10
// speedup vs baseline: 4.1851x; 1.3500x over previous
#include <cuda_runtime.h>
#include <cuda_fp16.h>
#include <math.h>
#include <stdint.h>

#define L_   12
#define S_   512
#define B_   4
#define DIN_ 768
#define D_   1024
#define H_   16
#define F_   4096
#define HD_  64
#define SB_  2048
#define BH_  (B_*H_)
#define DD_  (D_*D_)
#define DF_  (D_*F_)

typedef __half f16;

// ---------------- persistent scratch (device globals) ----------------
__device__ __align__(16) f16 g_wqkv_h[(size_t)L_*3*DD_];
__device__ __align__(16) f16 g_wo_h  [(size_t)L_*DD_];
__device__ __align__(16) f16 g_w1_h  [(size_t)L_*DF_];
__device__ __align__(16) f16 g_w2_h  [(size_t)L_*DF_];
__device__ __align__(16) f16 g_wp_h  [DIN_*D_];
__device__ float g_bqkv[L_*3*D_];
__device__ __align__(16) f16 g_seg_h[SB_*DIN_];
__device__ __align__(16) f16 g_seg_l[SB_*DIN_];
__device__ __align__(16) f16 g_hh[SB_*D_];
__device__ __align__(16) f16 g_hl[SB_*D_];
__device__ __align__(16) f16 g_ah[SB_*D_];
__device__ __align__(16) f16 g_al[SB_*D_];
__device__ __align__(16) f16 g_ffh[(size_t)SB_*F_];
__device__ __align__(16) f16 g_ffl[(size_t)SB_*F_];
__device__ __align__(16) f16 g_qh[SB_*D_];
__device__ __align__(16) f16 g_ql[SB_*D_];
__device__ __align__(16) f16 g_kh[SB_*D_];
__device__ __align__(16) f16 g_vh[SB_*D_];
__device__ unsigned char g_mask8[B_*S_];
__device__ int   g_mask_mode;

// ============================================================================
// helpers
// ============================================================================
__device__ __forceinline__ uint32_t smem_u32(const void* p) {
    uint32_t a;
    asm("{ .reg .u64 t; cvta.to.shared.u64 t, %1; cvt.u32.u64 %0, t; }"
        : "=r"(a) : "l"(p));
    return a;
}
__device__ __forceinline__ void ldsm4(uint32_t* r, uint32_t addr) {
    asm volatile("ldmatrix.sync.aligned.m8n8.x4.shared.b16 {%0,%1,%2,%3}, [%4];"
                 : "=r"(r[0]), "=r"(r[1]), "=r"(r[2]), "=r"(r[3]) : "r"(addr));
}
__device__ __forceinline__ void ldsm4t(uint32_t* r, uint32_t addr) {
    asm volatile("ldmatrix.sync.aligned.m8n8.x4.trans.shared.b16 {%0,%1,%2,%3}, [%4];"
                 : "=r"(r[0]), "=r"(r[1]), "=r"(r[2]), "=r"(r[3]) : "r"(addr));
}
__device__ __forceinline__ void mma16816(float* d, const uint32_t* a, const uint32_t* b) {
    asm volatile(
        "mma.sync.aligned.m16n8k16.row.col.f32.f16.f16.f32 "
        "{%0,%1,%2,%3}, {%4,%5,%6,%7}, {%8,%9}, {%0,%1,%2,%3};"
        : "+f"(d[0]), "+f"(d[1]), "+f"(d[2]), "+f"(d[3])
        : "r"(a[0]), "r"(a[1]), "r"(a[2]), "r"(a[3]), "r"(b[0]), "r"(b[1]));
}
#define CP_ASYNC(dst, src) \
    asm volatile("cp.async.cg.shared.global [%0], [%1], 16;" :: "r"(dst), "l"(src))
#define CP_COMMIT() asm volatile("cp.async.commit_group;")
#define CP_WAIT(n)  asm volatile("cp.async.wait_group %0;" :: "n"(n))

__device__ __forceinline__ void split2(float v0, float v1, uint32_t& hi, uint32_t& lo) {
    __half2 h = __floats2half2_rn(v0, v1);
    __half2 l = __floats2half2_rn(v0 - __half2float(h.x), v1 - __half2float(h.y));
    hi = *(uint32_t*)&h; lo = *(uint32_t*)&l;
}
__device__ __forceinline__ uint32_t pack2h(float v0, float v1) {
    __half2 h = __floats2half2_rn(v0, v1);
    return *(uint32_t*)&h;
}

// ============================================================================
// conversions (vectorized x4)
// ============================================================================
__global__ void conv_split4(const float4* __restrict__ src, f16* __restrict__ dh,
                            f16* __restrict__ dl, int n4) {
    int i = blockIdx.x * blockDim.x + threadIdx.x;
    if (i >= n4) return;
    float4 v = src[i];
    uint32_t h01, l01, h23, l23;
    split2(v.x, v.y, h01, l01);
    split2(v.z, v.w, h23, l23);
    *(uint2*)(dh + (size_t)i * 4) = make_uint2(h01, h23);
    *(uint2*)(dl + (size_t)i * 4) = make_uint2(l01, l23);
}
__global__ void conv_hi4(const float4* __restrict__ src, f16* __restrict__ dh,
                         int n4, int inner4, int gm, int go) {
    int i = blockIdx.x * blockDim.x + threadIdx.x;
    if (i >= n4) return;
    float4 v = src[i];
    size_t d = ((size_t)(i / inner4) * inner4 * gm + (size_t)go * inner4 + (i % inner4)) * 4;
    *(uint2*)(dh + d) = make_uint2(pack2h(v.x, v.y), pack2h(v.z, v.w));
}
__global__ void map_bias(const float* __restrict__ src, float* __restrict__ dst,
                         int n, int inner, int gm, int go) {
    int i = blockIdx.x * blockDim.x + threadIdx.x;
    if (i >= n) return;
    dst[(size_t)(i / inner) * inner * gm + (size_t)go * inner + (i % inner)] = src[i];
}

// ---------------- mask: detect dtype, canonicalize to u8 ----------------
__global__ void detect_mask_kernel(const void* m) {
    __shared__ int flags[2];
    if (threadIdx.x == 0) { flags[0] = 0; flags[1] = 0; }
    __syncthreads();
    unsigned v = ((const unsigned*)m)[threadIdx.x];
    if (v > 1u) flags[0] = 1;
    if (v != 0u && v != 0x3F800000u) flags[1] = 1;
    __syncthreads();
    if (threadIdx.x == 0)
        g_mask_mode = (!flags[0]) ? 1 : ((!flags[1]) ? 2 : 0);
}
__global__ void mask8_kernel(const void* m) {
    int i = blockIdx.x * blockDim.x + threadIdx.x;
    int mode = g_mask_mode;
    unsigned char r;
    if (mode == 1)      r = ((const int*)m)[i] != 0;
    else if (mode == 2) r = ((const float*)m)[i] != 0.f;
    else                r = ((const unsigned char*)m)[i] != 0;
    g_mask8[i] = r;
}

// ============================================================================
// fp16 2-term HMMA GEMM: C = A[M,K] @ W[K,N], A split (h+l), W hi only.
// MODE 0: C = acc+bias   MODE 1: C += acc+bias
// MODE 2: CH/CL = split(gelu(acc+bias))
// MODE 3: QKV: z=0 rope->qh/ql, z=1 rope->kh, z=2 ->vh
// ============================================================================
#define A_STRIDE   80
#define B_STRIDE   272
#define AH_OFF     0
#define AL_OFF     10240
#define BH_OFF     20480
#define STAGE_B    29184
#define GEMM_SMEM  (2*STAGE_B)

__device__ __forceinline__ void load_stage(
    const f16* __restrict__ AH, const f16* __restrict__ AL,
    const f16* __restrict__ WH,
    int K, int N, int rowBase, int colBase, int ck, uint32_t st, int tid)
{
#pragma unroll
    for (int t = 0; t < 4; t++) {
        int idx = tid + t * 256;
        int tile = idx >> 9;
        int r = (idx >> 2) & 127;
        int c16 = idx & 3;
        const f16* src = (tile ? AL : AH) + (size_t)(rowBase + r) * K + ck + c16 * 8;
        uint32_t dst = st + (tile ? AL_OFF : AH_OFF) + r * A_STRIDE + c16 * 16;
        CP_ASYNC(dst, src);
    }
#pragma unroll
    for (int t = 0; t < 2; t++) {
        int idx = tid + t * 256;
        int r = (idx >> 4) & 31;
        int c16 = idx & 15;
        const f16* src = WH + (size_t)(ck + r) * N + colBase + c16 * 8;
        uint32_t dst = st + BH_OFF + r * B_STRIDE + c16 * 16;
        CP_ASYNC(dst, src);
    }
}

template<int MODE>
__global__ void __launch_bounds__(256, 2) hmma2(
    const f16* __restrict__ AH, const f16* __restrict__ AL,
    const f16* __restrict__ WH,
    const float* __restrict__ bias, float* __restrict__ C,
    f16* __restrict__ CH, f16* __restrict__ CL,
    f16* __restrict__ o1h, f16* __restrict__ o2h,
    int M, int N, int K, long long Wz, long long bz)
{
    extern __shared__ char smem[];
    const int z = blockIdx.z;
    WH += (size_t)z * Wz; bias += (size_t)z * bz;

    const int tid  = threadIdx.x;
    const int lane = tid & 31;
    const int wid  = tid >> 5;
    const int m0   = (wid & 3) << 5;
    const int n0w  = (wid >> 2) << 6;
    const int rowBase = blockIdx.y << 7;
    const int colBase = blockIdx.x << 7;
    const int NC = K >> 5;

    uint32_t sbase = smem_u32(smem);

    float acc[2][8][4];
#pragma unroll
    for (int a = 0; a < 2; a++)
#pragma unroll
        for (int b = 0; b < 8; b++)
#pragma unroll
            for (int c = 0; c < 4; c++) acc[a][b][c] = 0.f;

    load_stage(AH, AL, WH, K, N, rowBase, colBase, 0, sbase, tid);
    CP_COMMIT();
    load_stage(AH, AL, WH, K, N, rowBase, colBase, 32, sbase + STAGE_B, tid);
    CP_COMMIT();
    CP_WAIT(1);
    __syncthreads();

    const int arow = lane & 15;
    const int aoff = (lane >> 4) << 4;

    for (int c = 0; c < NC; c++) {
        uint32_t cur = sbase + (c & 1) * STAGE_B;
#pragma unroll
        for (int ks = 0; ks < 32; ks += 16) {
            uint32_t ah[2][4], al[2][4];
#pragma unroll
            for (int mt = 0; mt < 2; mt++) {
                uint32_t ad = cur + (uint32_t)((m0 + mt * 16 + arow) * A_STRIDE + ks * 2 + aoff);
                ldsm4(ah[mt], ad);
                ldsm4(al[mt], ad + AL_OFF);
            }
#pragma unroll
            for (int np = 0; np < 4; np++) {
                uint32_t bh[4];
                uint32_t bd = cur + BH_OFF +
                    (uint32_t)((ks + arow) * B_STRIDE + ((n0w + np * 16) << 1) + aoff);
                ldsm4t(bh, bd);
#pragma unroll
                for (int mt = 0; mt < 2; mt++)
#pragma unroll
                    for (int e = 0; e < 2; e++) {
                        uint32_t bfh[2] = { bh[2 * e], bh[2 * e + 1] };
                        float* d = acc[mt][np * 2 + e];
                        mma16816(d, ah[mt], bfh);
                        mma16816(d, al[mt], bfh);
                    }
            }
        }
        __syncthreads();
        if (c + 2 < NC) {
            load_stage(AH, AL, WH, K, N, rowBase, colBase, (c + 2) << 5,
                       sbase + (c & 1) * STAGE_B, tid);
            CP_COMMIT();
            CP_WAIT(1);
        } else {
            CP_WAIT(0);
        }
        __syncthreads();
    }

    // ---- epilogue ----
    if (MODE == 3) {
#pragma unroll
        for (int mt = 0; mt < 2; mt++) {
#pragma unroll
            for (int half = 0; half < 2; half++) {
                const int row = rowBase + m0 + mt * 16 + (lane >> 2) + half * 8;
                const int s = row >> 2;
                if (z < 2) {
#pragma unroll
                    for (int nt = 0; nt < 4; nt++) {
                        const int c0 = colBase + n0w + (nt << 3) + ((lane & 3) << 1);
                        float v0 = acc[mt][nt][half * 2 + 0] + bias[c0];
                        float v1 = acc[mt][nt][half * 2 + 1] + bias[c0 + 1];
                        float w0 = acc[mt][nt + 4][half * 2 + 0] + bias[c0 + 32];
                        float w1 = acc[mt][nt + 4][half * 2 + 1] + bias[c0 + 33];
                        int i0 = c0 & 63;
                        float th0 = (float)s * expf(-0.28782313662425572f * (float)i0);
                        float th1 = (float)s * expf(-0.28782313662425572f * (float)(i0 + 1));
                        float c0s, s0s, c1s, s1s;
                        sincosf(th0, &s0s, &c0s);
                        sincosf(th1, &s1s, &c1s);
                        float y0 = v0 * c0s - w0 * s0s, zz0 = w0 * c0s + v0 * s0s;
                        float y1 = v1 * c1s - w1 * s1s, zz1 = w1 * c1s + v1 * s1s;
                        if (z == 0) {
                            uint32_t hi, lo;
                            split2(y0, y1, hi, lo);
                            *(uint32_t*)(CH + (size_t)row * D_ + c0) = hi;
                            *(uint32_t*)(CL + (size_t)row * D_ + c0) = lo;
                            split2(zz0, zz1, hi, lo);
                            *(uint32_t*)(CH + (size_t)row * D_ + c0 + 32) = hi;
                            *(uint32_t*)(CL + (size_t)row * D_ + c0 + 32) = lo;
                        } else {
                            *(uint32_t*)(o1h + (size_t)row * D_ + c0) = pack2h(y0, y1);
                            *(uint32_t*)(o1h + (size_t)row * D_ + c0 + 32) = pack2h(zz0, zz1);
                        }
                    }
                } else {
#pragma unroll
                    for (int nt = 0; nt < 8; nt++) {
                        const int c0 = colBase + n0w + (nt << 3) + ((lane & 3) << 1);
                        float v0 = acc[mt][nt][half * 2 + 0] + bias[c0];
                        float v1 = acc[mt][nt][half * 2 + 1] + bias[c0 + 1];
                        *(uint32_t*)(o2h + (size_t)row * D_ + c0) = pack2h(v0, v1);
                    }
                }
            }
        }
        return;
    }

#pragma unroll
    for (int mt = 0; mt < 2; mt++) {
        const int r0 = rowBase + m0 + mt * 16 + (lane >> 2);
#pragma unroll
        for (int nt = 0; nt < 8; nt++) {
            const int c0 = colBase + n0w + nt * 8 + ((lane & 3) << 1);
            float* d = acc[mt][nt];
            float b0 = bias[c0], b1 = bias[c0 + 1];
#pragma unroll
            for (int half = 0; half < 2; half++) {
                const int row = r0 + half * 8;
                float v0 = d[half * 2 + 0] + b0;
                float v1 = d[half * 2 + 1] + b1;
                if (MODE == 0) {
                    float* out = C + (size_t)row * N + c0;
                    out[0] = v0; out[1] = v1;
                } else if (MODE == 1) {
                    float* out = C + (size_t)row * N + c0;
                    out[0] += v0; out[1] += v1;
                } else {
                    float g0 = 0.5f * v0 * (1.f + erff(v0 * 0.70710678118654752f));
                    float g1 = 0.5f * v1 * (1.f + erff(v1 * 0.70710678118654752f));
                    uint32_t hi, lo;
                    split2(g0, g1, hi, lo);
                    *(uint32_t*)(CH + (size_t)row * N + c0) = hi;
                    *(uint32_t*)(CL + (size_t)row * N + c0) = lo;
                }
            }
        }
    }
}

// ============================================================================
// Flash attention (fp16 2-term): Q split, K/V hi-only.
// smem: qh, ql + 2 KV buffers (kh, vh)
// ============================================================================
#define FA_STRIDE 144
#define FA_TILE   18432
#define FA_SMEM   (6*FA_TILE)    // 110592

__device__ __forceinline__ void fa_kv_load(
    const f16* __restrict__ kh, const f16* __restrict__ vh,
    size_t hoff, int krow0, uint32_t dst, int tid)
{
#pragma unroll
    for (int t = 0; t < 8; t++) {
        int idx = tid + t * 256;
        int tile = idx >> 10, rem = idx & 1023;
        int r = rem >> 3, c = rem & 7;
        const f16* base = tile ? vh : kh;
        const f16* src = base + hoff + (size_t)(krow0 + r) * (B_ * D_) + c * 8;
        CP_ASYNC(dst + tile * FA_TILE + r * FA_STRIDE + c * 16, src);
    }
}

__global__ void __launch_bounds__(256, 1) flash_attn(
    const f16* __restrict__ qh, const f16* __restrict__ ql,
    const f16* __restrict__ kh, const f16* __restrict__ vh,
    const unsigned char* __restrict__ mask8,
    f16* __restrict__ aH, f16* __restrict__ aL)
{
    extern __shared__ char smem[];
    const int bh = blockIdx.y;
    const int b = bh >> 4, h = bh & 15;
    const int q0 = blockIdx.x << 7;
    const int tid = threadIdx.x, lane = tid & 31, wid = tid >> 5;
    const int m0 = wid << 4;
    const size_t hoff = (size_t)b * D_ + h * HD_;
    uint32_t sb = smem_u32(smem);
    const uint32_t kv0 = sb + 2 * FA_TILE;
    const uint32_t kv1 = sb + 4 * FA_TILE;

#pragma unroll
    for (int t = 0; t < 8; t++) {
        int idx = tid + t * 256;
        int tile = idx >> 10, rem = idx & 1023;
        int r = rem >> 3, c = rem & 7;
        const f16* src = (tile ? ql : qh) + hoff + (size_t)(q0 + r) * (B_ * D_) + c * 8;
        CP_ASYNC(sb + tile * FA_TILE + r * FA_STRIDE + c * 16, src);
    }
    fa_kv_load(kh, vh, hoff, 0, kv0, tid);
    CP_COMMIT();
    fa_kv_load(kh, vh, hoff, 128, kv1, tid);
    CP_COMMIT();
    CP_WAIT(1);
    __syncthreads();

    float oacc[8][4];
#pragma unroll
    for (int i = 0; i < 8; i++)
#pragma unroll
        for (int j = 0; j < 4; j++) oacc[i][j] = 0.f;
    float mr0 = -1e30f, mr1 = -1e30f, l0 = 0.f, l1 = 0.f;

    const int arow = lane & 15;
    const int aoff = (lane >> 4) << 4;
    const unsigned char* mrow = mask8 + b * S_;

    for (int kt = 0; kt < 4; kt++) {
        const uint32_t kv = (kt & 1) ? kv1 : kv0;
        float sacc[16][4];
#pragma unroll
        for (int i = 0; i < 16; i++)
#pragma unroll
            for (int j = 0; j < 4; j++) sacc[i][j] = 0.f;

        // S = Q K^T (2-term: Q split, K hi)
#pragma unroll
        for (int kc = 0; kc < 4; kc++) {
            uint32_t qa = sb + (uint32_t)((m0 + arow) * FA_STRIDE + kc * 32 + aoff);
            uint32_t qhf[4], qlf[4];
            ldsm4(qhf, qa);
            ldsm4(qlf, qa + FA_TILE);
#pragma unroll
            for (int ng = 0; ng < 8; ng++) {
                uint32_t bhf[4];
                uint32_t ka = kv + (uint32_t)((ng * 16 + arow) * FA_STRIDE + kc * 32 + aoff);
                ldsm4(bhf, ka);
#pragma unroll
                for (int e = 0; e < 2; e++) {
                    uint32_t bh2[2] = { bhf[e], bhf[e + 2] };
                    float* d = sacc[ng * 2 + e];
                    mma16816(d, qhf, bh2);
                    mma16816(d, qlf, bh2);
                }
            }
        }

        // mask + scale + row max
        float mx0 = -1e30f, mx1 = -1e30f;
#pragma unroll
        for (int nt = 0; nt < 16; nt++) {
#pragma unroll
            for (int u = 0; u < 2; u++) {
                int col = (kt << 7) + (nt << 3) + ((lane & 3) << 1) + u;
                bool msk = mrow[col] != 0;
                float v0 = msk ? -1e30f : sacc[nt][u] * 0.125f;
                float v1 = msk ? -1e30f : sacc[nt][2 + u] * 0.125f;
                sacc[nt][u] = v0; sacc[nt][2 + u] = v1;
                mx0 = fmaxf(mx0, v0); mx1 = fmaxf(mx1, v1);
            }
        }
        mx0 = fmaxf(mx0, __shfl_xor_sync(0xFFFFFFFFu, mx0, 1));
        mx0 = fmaxf(mx0, __shfl_xor_sync(0xFFFFFFFFu, mx0, 2));
        mx1 = fmaxf(mx1, __shfl_xor_sync(0xFFFFFFFFu, mx1, 1));
        mx1 = fmaxf(mx1, __shfl_xor_sync(0xFFFFFFFFu, mx1, 2));
        float mn0 = fmaxf(mr0, mx0), mn1 = fmaxf(mr1, mx1);
        float al0 = __expf(mr0 - mn0), al1 = __expf(mr1 - mn1);
        mr0 = mn0; mr1 = mn1;

        float s0 = 0.f, s1 = 0.f;
#pragma unroll
        for (int nt = 0; nt < 16; nt++) {
            float p0 = __expf(sacc[nt][0] - mn0);
            float p1 = __expf(sacc[nt][1] - mn0);
            float p2 = __expf(sacc[nt][2] - mn1);
            float p3 = __expf(sacc[nt][3] - mn1);
            sacc[nt][0] = p0; sacc[nt][1] = p1; sacc[nt][2] = p2; sacc[nt][3] = p3;
            s0 += p0 + p1; s1 += p2 + p3;
        }
        s0 += __shfl_xor_sync(0xFFFFFFFFu, s0, 1);
        s0 += __shfl_xor_sync(0xFFFFFFFFu, s0, 2);
        s1 += __shfl_xor_sync(0xFFFFFFFFu, s1, 1);
        s1 += __shfl_xor_sync(0xFFFFFFFFu, s1, 2);
        l0 = l0 * al0 + s0;
        l1 = l1 * al1 + s1;
#pragma unroll
        for (int nt = 0; nt < 8; nt++) {
            oacc[nt][0] *= al0; oacc[nt][1] *= al0;
            oacc[nt][2] *= al1; oacc[nt][3] *= al1;
        }

        // O += P V (2-term: P split, V hi)
#pragma unroll
        for (int kc2 = 0; kc2 < 8; kc2++) {
            uint32_t pa_h[4], pa_l[4];
            split2(sacc[2 * kc2][0],     sacc[2 * kc2][1],     pa_h[0], pa_l[0]);
            split2(sacc[2 * kc2][2],     sacc[2 * kc2][3],     pa_h[1], pa_l[1]);
            split2(sacc[2 * kc2 + 1][0], sacc[2 * kc2 + 1][1], pa_h[2], pa_l[2]);
            split2(sacc[2 * kc2 + 1][2], sacc[2 * kc2 + 1][3], pa_h[3], pa_l[3]);
#pragma unroll
            for (int ng = 0; ng < 4; ng++) {
                uint32_t bhf[4];
                uint32_t va = kv + FA_TILE +
                    (uint32_t)((kc2 * 16 + arow) * FA_STRIDE + ng * 32 + aoff);
                ldsm4t(bhf, va);
#pragma unroll
                for (int e = 0; e < 2; e++) {
                    uint32_t bh2[2] = { bhf[2 * e], bhf[2 * e + 1] };
                    float* d = oacc[ng * 2 + e];
                    mma16816(d, pa_h, bh2);
                    mma16816(d, pa_l, bh2);
                }
            }
        }

        __syncthreads();
        if (kt + 2 < 4) {
            fa_kv_load(kh, vh, hoff, (kt + 2) << 7, kv, tid);
            CP_COMMIT();
            CP_WAIT(1);
            __syncthreads();
        } else if (kt + 1 < 4) {
            CP_WAIT(0);
            __syncthreads();
        }
    }

    float inv0 = 1.f / l0, inv1 = 1.f / l1;
    const int r0 = q0 + m0 + (lane >> 2);
#pragma unroll
    for (int nt = 0; nt < 8; nt++) {
        const int c0 = (nt << 3) + ((lane & 3) << 1);
        uint32_t hi, lo;
        split2(oacc[nt][0] * inv0, oacc[nt][1] * inv0, hi, lo);
        size_t a0 = hoff + (size_t)r0 * (B_ * D_) + c0;
        *(uint32_t*)(aH + a0) = hi;
        *(uint32_t*)(aL + a0) = lo;
        split2(oacc[nt][2] * inv1, oacc[nt][3] * inv1, hi, lo);
        size_t a1 = hoff + (size_t)(r0 + 8) * (B_ * D_) + c0;
        *(uint32_t*)(aH + a1) = hi;
        *(uint32_t*)(aL + a1) = lo;
    }
}

// ---------------- LayerNorm -> split fp16 ----------------
__global__ __launch_bounds__(256) void ln_kernel(
    const float* __restrict__ x, const float* __restrict__ g,
    const float* __restrict__ b, f16* __restrict__ outH, f16* __restrict__ outL)
{
    int row = blockIdx.x;
    int tid = threadIdx.x;
    const float* xr = x + (size_t)row * D_;
    float4 v = *(const float4*)(xr + tid * 4);
    float s  = v.x + v.y + v.z + v.w;
    float s2 = v.x * v.x + v.y * v.y + v.z * v.z + v.w * v.w;
    __shared__ float r1[256], r2[256];
    r1[tid] = s; r2[tid] = s2;
    __syncthreads();
    for (int off = 128; off > 0; off >>= 1) {
        if (tid < off) { r1[tid] += r1[tid + off]; r2[tid] += r2[tid + off]; }
        __syncthreads();
    }
    float mean = r1[0] * (1.f / D_);
    float var  = r2[0] * (1.f / D_) - mean * mean;
    float rstd = rsqrtf(var + 1e-5f);
    float4 gv = *(const float4*)(g + tid * 4);
    float4 bv = *(const float4*)(b + tid * 4);
    float o0 = (v.x - mean) * rstd * gv.x + bv.x;
    float o1 = (v.y - mean) * rstd * gv.y + bv.y;
    float o2 = (v.z - mean) * rstd * gv.z + bv.z;
    float o3 = (v.w - mean) * rstd * gv.w + bv.w;
    uint32_t h01, l01, h23, l23;
    split2(o0, o1, h01, l01);
    split2(o2, o3, h23, l23);
    size_t base = (size_t)row * D_ + tid * 4;
    *(uint2*)(outH + base) = make_uint2(h01, h23);
    *(uint2*)(outL + base) = make_uint2(l01, l23);
}

// ---------------- x += dur[r]*Wdur[c] + bdur[c] ----------------
__global__ void adddur_kernel(float* __restrict__ x, const float* __restrict__ dur,
                              const float* __restrict__ wd, const float* __restrict__ bd) {
    int idx = blockIdx.x * blockDim.x + threadIdx.x;
    int r = idx >> 10, c = idx & 1023;
    x[idx] += dur[r] * wd[c] + bd[c];
}

// ---------------- host orchestration ----------------
extern "C" void kernel_launch(void* const* d_in, const int* in_sizes, int n_in,
                              void* d_out, int out_size)
{
    (void)in_sizes; (void)n_in; (void)out_size;
    const float* segments  = (const float*)d_in[0];
    const float* durations = (const float*)d_in[1];
    const void*  mask      = d_in[2];
    const float* Wproj = (const float*)d_in[3];
    const float* bproj = (const float*)d_in[4];
    const float* Wdur  = (const float*)d_in[5];
    const float* bdur  = (const float*)d_in[6];
    const float* ln1g  = (const float*)d_in[7];
    const float* ln1b  = (const float*)d_in[8];
    const float* Wq    = (const float*)d_in[9];
    const float* bq    = (const float*)d_in[10];
    const float* Wk    = (const float*)d_in[11];
    const float* bk    = (const float*)d_in[12];
    const float* Wv    = (const float*)d_in[13];
    const float* bv    = (const float*)d_in[14];
    const float* Wo    = (const float*)d_in[15];
    const float* bo    = (const float*)d_in[16];
    const float* ln2g  = (const float*)d_in[17];
    const float* ln2b  = (const float*)d_in[18];
    const float* W1    = (const float*)d_in[19];
    const float* b1    = (const float*)d_in[20];
    const float* W2    = (const float*)d_in[21];
    const float* b2    = (const float*)d_in[22];
    float* x = (float*)d_out;

    f16 *wqkvH, *woH, *w1H, *w2H, *wpH;
    f16 *segH, *segL, *hH, *hL, *aH, *aL, *ffH, *ffL;
    f16 *qh, *ql, *kh, *vh;
    float *bqkv;
    unsigned char* mask8;
    cudaGetSymbolAddress((void**)&wqkvH, g_wqkv_h);
    cudaGetSymbolAddress((void**)&woH,   g_wo_h);
    cudaGetSymbolAddress((void**)&w1H,   g_w1_h);
    cudaGetSymbolAddress((void**)&w2H,   g_w2_h);
    cudaGetSymbolAddress((void**)&wpH,   g_wp_h);
    cudaGetSymbolAddress((void**)&segH,  g_seg_h);
    cudaGetSymbolAddress((void**)&segL,  g_seg_l);
    cudaGetSymbolAddress((void**)&hH,    g_hh);
    cudaGetSymbolAddress((void**)&hL,    g_hl);
    cudaGetSymbolAddress((void**)&aH,    g_ah);
    cudaGetSymbolAddress((void**)&aL,    g_al);
    cudaGetSymbolAddress((void**)&ffH,   g_ffh);
    cudaGetSymbolAddress((void**)&ffL,   g_ffl);
    cudaGetSymbolAddress((void**)&bqkv,  g_bqkv);
    cudaGetSymbolAddress((void**)&qh, g_qh);
    cudaGetSymbolAddress((void**)&ql, g_ql);
    cudaGetSymbolAddress((void**)&kh, g_kh);
    cudaGetSymbolAddress((void**)&vh, g_vh);
    cudaGetSymbolAddress((void**)&mask8, g_mask8);

    cudaFuncSetAttribute(hmma2<0>, cudaFuncAttributeMaxDynamicSharedMemorySize, GEMM_SMEM);
    cudaFuncSetAttribute(hmma2<1>, cudaFuncAttributeMaxDynamicSharedMemorySize, GEMM_SMEM);
    cudaFuncSetAttribute(hmma2<2>, cudaFuncAttributeMaxDynamicSharedMemorySize, GEMM_SMEM);
    cudaFuncSetAttribute(hmma2<3>, cudaFuncAttributeMaxDynamicSharedMemorySize, GEMM_SMEM);
    cudaFuncSetAttribute(flash_attn, cudaFuncAttributeMaxDynamicSharedMemorySize, FA_SMEM);

    detect_mask_kernel<<<1, 512>>>(mask);
    mask8_kernel<<<8, 256>>>(mask);

    const int CT = 256;
    int n4;
    n4 = (L_ * DD_) / 4;
    conv_hi4<<<(n4 + CT - 1) / CT, CT>>>((const float4*)Wq, wqkvH, n4, DD_ / 4, 3, 0);
    conv_hi4<<<(n4 + CT - 1) / CT, CT>>>((const float4*)Wk, wqkvH, n4, DD_ / 4, 3, 1);
    conv_hi4<<<(n4 + CT - 1) / CT, CT>>>((const float4*)Wv, wqkvH, n4, DD_ / 4, 3, 2);
    conv_hi4<<<(n4 + CT - 1) / CT, CT>>>((const float4*)Wo, woH, n4, 1, 1, 0);
    n4 = (L_ * DF_) / 4;
    conv_hi4<<<(n4 + CT - 1) / CT, CT>>>((const float4*)W1, w1H, n4, 1, 1, 0);
    conv_hi4<<<(n4 + CT - 1) / CT, CT>>>((const float4*)W2, w2H, n4, 1, 1, 0);
    n4 = (DIN_ * D_) / 4;
    conv_hi4<<<(n4 + CT - 1) / CT, CT>>>((const float4*)Wproj, wpH, n4, 1, 1, 0);
    n4 = (SB_ * DIN_) / 4;
    conv_split4<<<(n4 + CT - 1) / CT, CT>>>((const float4*)segments, segH, segL, n4);
    int nb = L_ * D_;
    map_bias<<<(nb + CT - 1) / CT, CT>>>(bq, bqkv, nb, D_, 3, 0);
    map_bias<<<(nb + CT - 1) / CT, CT>>>(bk, bqkv, nb, D_, 3, 1);
    map_bias<<<(nb + CT - 1) / CT, CT>>>(bv, bqkv, nb, D_, 3, 2);

    dim3 gD(D_ / 128, SB_ / 128);
    dim3 gQKV(D_ / 128, SB_ / 128, 3);
    dim3 gF(F_ / 128, SB_ / 128);

    hmma2<0><<<gD, 256, GEMM_SMEM>>>(segH, segL, wpH, bproj, x,
        nullptr, nullptr, nullptr, nullptr, SB_, D_, DIN_, 0, 0);
    adddur_kernel<<<(SB_ * D_) / 256, 256>>>(x, durations, Wdur, bdur);

    for (int l = 0; l < L_; l++) {
        ln_kernel<<<SB_, 256>>>(x, ln1g + (size_t)l * D_, ln1b + (size_t)l * D_, hH, hL);
        hmma2<3><<<gQKV, 256, GEMM_SMEM>>>(hH, hL,
            wqkvH + (size_t)l * 3 * DD_,
            bqkv + (size_t)l * 3 * D_, nullptr,
            qh, ql, kh, vh,
            SB_, D_, D_, DD_, D_);
        flash_attn<<<dim3(4, BH_), 256, FA_SMEM>>>(qh, ql, kh, vh, mask8, aH, aL);
        hmma2<1><<<gD, 256, GEMM_SMEM>>>(aH, aL,
            woH + (size_t)l * DD_,
            bo + (size_t)l * D_, x,
            nullptr, nullptr, nullptr, nullptr, SB_, D_, D_, 0, 0);
        ln_kernel<<<SB_, 256>>>(x, ln2g + (size_t)l * D_, ln2b + (size_t)l * D_, hH, hL);
        hmma2<2><<<gF, 256, GEMM_SMEM>>>(hH, hL,
            w1H + (size_t)l * DF_,
            b1 + (size_t)l * F_, nullptr,
            ffH, ffL, nullptr, nullptr, SB_, F_, D_, 0, 0);
        hmma2<1><<<gD, 256, GEMM_SMEM>>>(ffH, ffL,
            w2H + (size_t)l * DF_,
            b2 + (size_t)l * D_, x,
            nullptr, nullptr, nullptr, nullptr, SB_, D_, F_, 0, 0);
    }
}